// round 1
// baseline (speedup 1.0000x reference)
#include <cuda_runtime.h>

// ---------------------------------------------------------------------------
// MultiHeadCrossAttn: h[1024,4,1024], c[2048,4,1024]
//   Q = h @ Wq^T ; K,V = c @ Wkv^T ; attn per (batch,head) with softmax over j
//   out = LN(h + (P V) @ Wo^T)
// All fp32. Scratch in __device__ globals (no allocations).
// ---------------------------------------------------------------------------

#define NH 16
#define DH 64
#define DM 1024
#define QL 1024
#define KVL 2048
#define BB 4
#define QROWS (QL*BB)     // 4096
#define KVROWS (KVL*BB)   // 8192
#define ATTN_SCALE 0.125f // 1/sqrt(64)

__device__ float g_Q [QROWS * DM];          // [i*BB+b][n*64+d]      16 MB
__device__ float g_KV[KVROWS * 2 * DM];     // [j*BB+b][K:0..1023 | V:1024..2047] 64 MB
__device__ float g_AV[QROWS * DM];          // attn output            16 MB
__device__ float g_Y [QROWS * DM];          // O-proj + residual      16 MB

// ---------------------------------------------------------------------------
// SGEMM (NT): C[M,N] = A[M,K] * B[N,K]^T  (+ optional residual R[M,N])
// 128x128 block tile, BK=16, 256 threads, 8x8 per-thread microtile.
// ---------------------------------------------------------------------------
template<bool ADD_RES>
__global__ __launch_bounds__(256) void sgemm_nt(
    const float* __restrict__ A, const float* __restrict__ Bw,
    const float* __restrict__ R, float* __restrict__ C,
    int M, int N, int K)
{
    __shared__ float As[16][132];
    __shared__ float Bs[16][132];
    const int tid = threadIdx.x;
    const int tx = tid & 15, ty = tid >> 4;
    const int m0 = blockIdx.y * 128, n0 = blockIdx.x * 128;
    const int lrow = tid >> 2, lq = tid & 3;

    const float* Ab = A  + (size_t)m0 * K;
    const float* Bb = Bw + (size_t)n0 * K;

    float acc[8][8];
#pragma unroll
    for (int i = 0; i < 8; i++)
#pragma unroll
        for (int j = 0; j < 8; j++) acc[i][j] = 0.f;

    for (int k0 = 0; k0 < K; k0 += 16) {
#pragma unroll
        for (int l = 0; l < 2; l++) {
            int row = lrow + l * 64;
            float4 av = *(const float4*)(Ab + (size_t)row * K + k0 + lq * 4);
            As[lq*4+0][row] = av.x; As[lq*4+1][row] = av.y;
            As[lq*4+2][row] = av.z; As[lq*4+3][row] = av.w;
            float4 bv = *(const float4*)(Bb + (size_t)row * K + k0 + lq * 4);
            Bs[lq*4+0][row] = bv.x; Bs[lq*4+1][row] = bv.y;
            Bs[lq*4+2][row] = bv.z; Bs[lq*4+3][row] = bv.w;
        }
        __syncthreads();
#pragma unroll
        for (int k = 0; k < 16; k++) {
            float a[8], b[8];
            *(float4*)&a[0] = *(const float4*)&As[k][ty*8];
            *(float4*)&a[4] = *(const float4*)&As[k][ty*8+4];
            *(float4*)&b[0] = *(const float4*)&Bs[k][tx*8];
            *(float4*)&b[4] = *(const float4*)&Bs[k][tx*8+4];
#pragma unroll
            for (int i = 0; i < 8; i++)
#pragma unroll
                for (int j = 0; j < 8; j++)
                    acc[i][j] += a[i] * b[j];
        }
        __syncthreads();
    }

#pragma unroll
    for (int i = 0; i < 8; i++) {
        int row = m0 + ty*8 + i;
        size_t off = (size_t)row * N + n0 + tx*8;
        float4 c0, c1;
        c0.x = acc[i][0]; c0.y = acc[i][1]; c0.z = acc[i][2]; c0.w = acc[i][3];
        c1.x = acc[i][4]; c1.y = acc[i][5]; c1.z = acc[i][6]; c1.w = acc[i][7];
        if (ADD_RES) {
            float4 r0 = *(const float4*)(R + off);
            float4 r1 = *(const float4*)(R + off + 4);
            c0.x += r0.x; c0.y += r0.y; c0.z += r0.z; c0.w += r0.w;
            c1.x += r1.x; c1.y += r1.y; c1.z += r1.z; c1.w += r1.w;
        }
        *(float4*)(C + off)     = c0;
        *(float4*)(C + off + 4) = c1;
    }
}

// ---------------------------------------------------------------------------
// Flash-style attention. Block = (64-query tile) x head x batch, 256 threads.
// Online softmax over 32 key tiles of 64. Smem: Qs[d][68] (transposed),
// KP region (K tile [d][68] aliased by P tile [j][65]), Vs[j][64].
// ---------------------------------------------------------------------------
#define ATTN_SMEM ((64*68 + 64*68 + 64*64) * 4)

__global__ __launch_bounds__(256) void attn_kernel(
    const float* __restrict__ Q, const float* __restrict__ KV,
    float* __restrict__ O)
{
    extern __shared__ float sm[];
    float* Qs = sm;              // [d*68 + r]
    float* KP = sm + 64*68;      // K: [d*68 + j] ; P: [j*65 + r]
    float* Vs = KP + 64*68;      // [j*64 + d]

    const int qt = blockIdx.x, n = blockIdx.y, b = blockIdx.z;
    const int tid = threadIdx.x;
    const int tx = tid & 15, ty = tid >> 4;
    const int lrow = tid >> 2, lq = tid & 3;

    // Q tile: rows i_local = 0..63, 64 d, transposed into Qs[d][r]
    {
        const float* qb = Q + ((size_t)(qt*64 + lrow) * BB + b) * DM + n * DH;
#pragma unroll
        for (int u = 0; u < 4; u++) {
            int d = u*16 + lq*4;
            float4 v = *(const float4*)(qb + d);
            Qs[(d+0)*68 + lrow] = v.x;
            Qs[(d+1)*68 + lrow] = v.y;
            Qs[(d+2)*68 + lrow] = v.z;
            Qs[(d+3)*68 + lrow] = v.w;
        }
    }

    float o[4][4];
#pragma unroll
    for (int rr = 0; rr < 4; rr++)
#pragma unroll
        for (int cc = 0; cc < 4; cc++) o[rr][cc] = 0.f;
    float mrow[4] = {-1e30f, -1e30f, -1e30f, -1e30f};
    float lacc[4] = {0.f, 0.f, 0.f, 0.f};

    for (int jt = 0; jt < KVL/64; jt++) {
        __syncthreads();   // prior iter's P/V reads done
        {
            const float* kb = KV + ((size_t)(jt*64 + lrow) * BB + b) * (2*DM) + n * DH;
#pragma unroll
            for (int u = 0; u < 4; u++) {
                int d = u*16 + lq*4;
                float4 v = *(const float4*)(kb + d);
                KP[(d+0)*68 + lrow] = v.x;
                KP[(d+1)*68 + lrow] = v.y;
                KP[(d+2)*68 + lrow] = v.z;
                KP[(d+3)*68 + lrow] = v.w;
                float4 w = *(const float4*)(kb + DM + d);
                *(float4*)&Vs[lrow*64 + d] = w;
            }
        }
        __syncthreads();

        // S = Q K^T (64x64 tile, 4x4 per thread)
        float s[4][4];
#pragma unroll
        for (int rr = 0; rr < 4; rr++)
#pragma unroll
            for (int cc = 0; cc < 4; cc++) s[rr][cc] = 0.f;
#pragma unroll
        for (int d = 0; d < 64; d++) {
            float a[4], bb[4];
            *(float4*)a  = *(const float4*)&Qs[d*68 + ty*4];
            *(float4*)bb = *(const float4*)&KP[d*68 + tx*4];
#pragma unroll
            for (int rr = 0; rr < 4; rr++)
#pragma unroll
                for (int cc = 0; cc < 4; cc++)
                    s[rr][cc] += a[rr] * bb[cc];
        }

        // online softmax (row = query), reductions over the 16-lane tx group
        float p[4][4];
#pragma unroll
        for (int rr = 0; rr < 4; rr++) {
            float rmax = -1e30f;
#pragma unroll
            for (int cc = 0; cc < 4; cc++) {
                s[rr][cc] *= ATTN_SCALE;
                rmax = fmaxf(rmax, s[rr][cc]);
            }
#pragma unroll
            for (int msk = 8; msk; msk >>= 1)
                rmax = fmaxf(rmax, __shfl_xor_sync(0xffffffffu, rmax, msk));
            float mnew = fmaxf(mrow[rr], rmax);
            float fcor = __expf(mrow[rr] - mnew);
            mrow[rr] = mnew;
            float rs = 0.f;
#pragma unroll
            for (int cc = 0; cc < 4; cc++) {
                p[rr][cc] = __expf(s[rr][cc] - mnew);
                rs += p[rr][cc];
            }
#pragma unroll
            for (int msk = 8; msk; msk >>= 1)
                rs += __shfl_xor_sync(0xffffffffu, rs, msk);
            lacc[rr] = lacc[rr] * fcor + rs;
#pragma unroll
            for (int cc = 0; cc < 4; cc++) o[rr][cc] *= fcor;
        }

        __syncthreads();   // K-tile reads done; reuse region as P
#pragma unroll
        for (int rr = 0; rr < 4; rr++)
#pragma unroll
            for (int cc = 0; cc < 4; cc++)
                KP[(tx*4+cc)*65 + ty*4+rr] = p[rr][cc];
        __syncthreads();

        // O += P V
#pragma unroll 8
        for (int j = 0; j < 64; j++) {
            float4 vb = *(const float4*)&Vs[j*64 + tx*4];
            float a0 = KP[j*65 + ty*4+0];
            float a1 = KP[j*65 + ty*4+1];
            float a2 = KP[j*65 + ty*4+2];
            float a3 = KP[j*65 + ty*4+3];
            o[0][0] += a0*vb.x; o[0][1] += a0*vb.y; o[0][2] += a0*vb.z; o[0][3] += a0*vb.w;
            o[1][0] += a1*vb.x; o[1][1] += a1*vb.y; o[1][2] += a1*vb.z; o[1][3] += a1*vb.w;
            o[2][0] += a2*vb.x; o[2][1] += a2*vb.y; o[2][2] += a2*vb.z; o[2][3] += a2*vb.w;
            o[3][0] += a3*vb.x; o[3][1] += a3*vb.y; o[3][2] += a3*vb.z; o[3][3] += a3*vb.w;
        }
    }

#pragma unroll
    for (int rr = 0; rr < 4; rr++) {
        float inv = 1.f / lacc[rr];
        int gi = qt*64 + ty*4 + rr;
        float4 ov;
        ov.x = o[rr][0]*inv; ov.y = o[rr][1]*inv;
        ov.z = o[rr][2]*inv; ov.w = o[rr][3]*inv;
        *(float4*)(O + ((size_t)gi * BB + b) * DM + n * DH + tx*4) = ov;
    }
}

// ---------------------------------------------------------------------------
// LayerNorm over rows of 1024 (input already contains residual).
// ---------------------------------------------------------------------------
__global__ __launch_bounds__(256) void ln_kernel(
    const float* __restrict__ Y, const float* __restrict__ gamma,
    const float* __restrict__ beta, float* __restrict__ out)
{
    __shared__ float red1[8];
    __shared__ float red2[8];
    const int row = blockIdx.x, tid = threadIdx.x;
    const float* y = Y + (size_t)row * DM;
    float v[4];
#pragma unroll
    for (int u = 0; u < 4; u++) v[u] = y[tid + u*256];

    float s = v[0] + v[1] + v[2] + v[3];
#pragma unroll
    for (int m = 16; m; m >>= 1) s += __shfl_xor_sync(0xffffffffu, s, m);
    if ((tid & 31) == 0) red1[tid >> 5] = s;
    __syncthreads();
    float tot = 0.f;
#pragma unroll
    for (int w = 0; w < 8; w++) tot += red1[w];
    float mu = tot * (1.f / DM);

    float q = 0.f;
#pragma unroll
    for (int u = 0; u < 4; u++) { float d = v[u] - mu; q += d * d; }
#pragma unroll
    for (int m = 16; m; m >>= 1) q += __shfl_xor_sync(0xffffffffu, q, m);
    if ((tid & 31) == 0) red2[tid >> 5] = q;
    __syncthreads();
    float qtot = 0.f;
#pragma unroll
    for (int w = 0; w < 8; w++) qtot += red2[w];
    float inv = rsqrtf(qtot * (1.f / DM) + 1e-5f);

#pragma unroll
    for (int u = 0; u < 4; u++) {
        int cix = tid + u*256;
        out[(size_t)row * DM + cix] = (v[u] - mu) * inv * gamma[cix] + beta[cix];
    }
}

// ---------------------------------------------------------------------------
extern "C" void kernel_launch(void* const* d_in, const int* in_sizes, int n_in,
                              void* d_out, int out_size)
{
    const float* h     = (const float*)d_in[0];
    const float* c     = (const float*)d_in[1];
    const float* Wq    = (const float*)d_in[2];
    const float* Wkv   = (const float*)d_in[3];
    const float* Wo    = (const float*)d_in[4];
    const float* gamma = (const float*)d_in[5];
    const float* beta  = (const float*)d_in[6];
    float* out = (float*)d_out;

    float *Qb, *KVb, *AVb, *Yb;
    cudaGetSymbolAddress((void**)&Qb,  g_Q);
    cudaGetSymbolAddress((void**)&KVb, g_KV);
    cudaGetSymbolAddress((void**)&AVb, g_AV);
    cudaGetSymbolAddress((void**)&Yb,  g_Y);

    cudaFuncSetAttribute(attn_kernel,
                         cudaFuncAttributeMaxDynamicSharedMemorySize, ATTN_SMEM);

    // Q = h @ Wq^T                  [4096 x 1024]
    sgemm_nt<false><<<dim3(DM/128, QROWS/128), 256>>>(h, Wq, nullptr, Qb,
                                                      QROWS, DM, DM);
    // KV = c @ Wkv^T                [8192 x 2048]
    sgemm_nt<false><<<dim3(2*DM/128, KVROWS/128), 256>>>(c, Wkv, nullptr, KVb,
                                                         KVROWS, 2*DM, DM);
    // attention -> AV               [4096 x 1024]
    attn_kernel<<<dim3(QL/64, NH, BB), 256, ATTN_SMEM>>>(Qb, KVb, AVb);
    // Y = AV @ Wo^T + h             [4096 x 1024]
    sgemm_nt<true><<<dim3(DM/128, QROWS/128), 256>>>(AVb, Wo, h, Yb,
                                                     QROWS, DM, DM);
    // out = LN(Y)
    ln_kernel<<<QROWS, 256>>>(Yb, gamma, beta, out);
}

// round 4
// speedup vs baseline: 1.2397x; 1.2397x over previous
#include <cuda_runtime.h>
#include <cuda_bf16.h>
#include <cstdint>

// ---------------------------------------------------------------------------
// MultiHeadCrossAttn on sm_100 (base target: no tcgen05; legacy mma.sync OK).
//  Projections: mma.sync m16n8k16 bf16 with 3-term fp32 emulation (bf16x3).
//  Attention:   fp32 SIMT flash-style.
//  LN:          fp32 two-pass.
// ---------------------------------------------------------------------------

#define NH 16
#define DH 64
#define DM 1024
#define QL 1024
#define KVL 2048
#define BB 4
#define QROWS (QL*BB)     // 4096
#define KVROWS (KVL*BB)   // 8192
#define ATTN_SCALE 0.125f

__device__ float g_Q [QROWS * DM];
__device__ float g_KV[KVROWS * 2 * DM];
__device__ float g_AV[QROWS * DM];
__device__ float g_Y [QROWS * DM];

// ------------------------------- helpers -----------------------------------
__device__ __forceinline__ uint32_t smem_u32(const void* p) {
    uint32_t a;
    asm("{ .reg .u64 t; cvta.to.shared.u64 t, %1; cvt.u32.u64 %0, t; }"
        : "=r"(a) : "l"(p));
    return a;
}

__device__ __forceinline__ void ldsm_x4(uint32_t& r0, uint32_t& r1,
                                        uint32_t& r2, uint32_t& r3, uint32_t addr) {
    asm volatile("ldmatrix.sync.aligned.m8n8.x4.shared.b16 {%0,%1,%2,%3}, [%4];"
                 : "=r"(r0), "=r"(r1), "=r"(r2), "=r"(r3) : "r"(addr));
}
__device__ __forceinline__ void ldsm_x2(uint32_t& r0, uint32_t& r1, uint32_t addr) {
    asm volatile("ldmatrix.sync.aligned.m8n8.x2.shared.b16 {%0,%1}, [%2];"
                 : "=r"(r0), "=r"(r1) : "r"(addr));
}
__device__ __forceinline__ void mma16816(float* c, const uint32_t* a, const uint32_t* b) {
    asm volatile("mma.sync.aligned.m16n8k16.row.col.f32.bf16.bf16.f32 "
                 "{%0,%1,%2,%3}, {%4,%5,%6,%7}, {%8,%9}, {%0,%1,%2,%3};"
                 : "+f"(c[0]), "+f"(c[1]), "+f"(c[2]), "+f"(c[3])
                 : "r"(a[0]), "r"(a[1]), "r"(a[2]), "r"(a[3]),
                   "r"(b[0]), "r"(b[1]));
}

// split two fp32 into packed bf16 hi pair + bf16 lo pair
__device__ __forceinline__ void split2(float x, float y, uint32_t& hi, uint32_t& lo) {
    __nv_bfloat16 hx = __float2bfloat16_rn(x);
    __nv_bfloat16 hy = __float2bfloat16_rn(y);
    float lxf = x - __bfloat162float(hx);
    float lyf = y - __bfloat162float(hy);
    __nv_bfloat16 lx = __float2bfloat16_rn(lxf);
    __nv_bfloat16 ly = __float2bfloat16_rn(lyf);
    hi = ((uint32_t)__bfloat16_as_ushort(hy) << 16) | __bfloat16_as_ushort(hx);
    lo = ((uint32_t)__bfloat16_as_ushort(ly) << 16) | __bfloat16_as_ushort(lx);
}

// ---------------------------------------------------------------------------
// bf16x3 GEMM (NT): C[M,N] = A[M,K] * B[N,K]^T (+residual)
// CTA 128x128, BK=32, 256 threads (8 warps, warp tile 64x32), 2-stage smem.
// SMEM rows: 32 bf16 = 64B data + 16B pad = 80B stride (conflict-free ldmatrix).
// ---------------------------------------------------------------------------
#define ROWB  80
#define AREG  10240              // 128 rows * 80B  (one operand, one precision)
#define STAGE 40960              // A_hi A_lo B_hi B_lo
#define GEMM_SMEM (2*STAGE)      // 81920

template<bool ADD_RES>
__global__ __launch_bounds__(256) void mma_gemm(
    const float* __restrict__ A, const float* __restrict__ Bw,
    const float* __restrict__ R, float* __restrict__ C,
    int M, int N, int K)
{
    extern __shared__ __align__(128) char sm[];
    const uint32_t sb = smem_u32(sm);
    const int tid = threadIdx.x;
    const int wid = tid >> 5, lane = tid & 31;
    const int m0 = blockIdx.y * 128, n0 = blockIdx.x * 128;

    const float* Ag = A  + (size_t)m0 * K;
    const float* Bg = Bw + (size_t)n0 * K;

    const int lrow = tid >> 3;        // 0..31 (row base; +32*i)
    const int lq   = tid & 7;         // float4 index within row

    const int wm = wid & 1, wn = wid >> 1;        // warp tile: (wm*64, wn*32)

    float acc[4][4][4];
#pragma unroll
    for (int mi = 0; mi < 4; mi++)
#pragma unroll
        for (int nj = 0; nj < 4; nj++)
#pragma unroll
            for (int e = 0; e < 4; e++) acc[mi][nj][e] = 0.f;

    // ldmatrix lane addressing
    const int l8   = lane & 7;
    const int arow = ((lane >> 3) & 1) * 8 + l8;          // x4 row within 16
    const int acol = ((lane >> 4) & 1) * 16;              // x4 k-byte half
    const int brow = (lane & 15) & 7;                     // x2: threads 0-15
    const int bcol = (((lane & 15) >> 3) & 1) * 16;

    const int nchunks = K >> 5;

    // staging registers for prefetch
    uint2 sA_h[4], sA_l[4], sB_h[4], sB_l[4];

    // prologue: chunk 0 -> stage 0
#pragma unroll
    for (int i = 0; i < 4; i++) {
        int row = lrow + i * 32;
        float4 v = *(const float4*)(Ag + (size_t)row * K + lq * 4);
        split2(v.x, v.y, sA_h[i].x, sA_l[i].x);
        split2(v.z, v.w, sA_h[i].y, sA_l[i].y);
        float4 w = *(const float4*)(Bg + (size_t)row * K + lq * 4);
        split2(w.x, w.y, sB_h[i].x, sB_l[i].x);
        split2(w.z, w.w, sB_h[i].y, sB_l[i].y);
    }
#pragma unroll
    for (int i = 0; i < 4; i++) {
        uint32_t off = (uint32_t)(lrow + i * 32) * ROWB + lq * 8;
        *(uint2*)(sm + off)            = sA_h[i];
        *(uint2*)(sm + off + AREG)     = sA_l[i];
        *(uint2*)(sm + off + 2*AREG)   = sB_h[i];
        *(uint2*)(sm + off + 3*AREG)   = sB_l[i];
    }
    __syncthreads();

    for (int kc = 0; kc < nchunks; kc++) {
        // prefetch next chunk into registers
        if (kc + 1 < nchunks) {
            const int kk = (kc + 1) << 5;
#pragma unroll
            for (int i = 0; i < 4; i++) {
                int row = lrow + i * 32;
                float4 v = *(const float4*)(Ag + (size_t)row * K + kk + lq * 4);
                split2(v.x, v.y, sA_h[i].x, sA_l[i].x);
                split2(v.z, v.w, sA_h[i].y, sA_l[i].y);
                float4 w = *(const float4*)(Bg + (size_t)row * K + kk + lq * 4);
                split2(w.x, w.y, sB_h[i].x, sB_l[i].x);
                split2(w.z, w.w, sB_h[i].y, sB_l[i].y);
            }
        }

        // compute current stage
        const uint32_t abase = sb + (uint32_t)(kc & 1) * STAGE;
        const uint32_t bbase = abase + 2 * AREG;
#pragma unroll
        for (int s = 0; s < 2; s++) {
            uint32_t bhf[4][2], blf[4][2];
#pragma unroll
            for (int nj = 0; nj < 4; nj++) {
                uint32_t baddr = bbase + (uint32_t)(wn*32 + nj*8 + brow) * ROWB
                               + s*32 + bcol;
                ldsm_x2(bhf[nj][0], bhf[nj][1], baddr);
                ldsm_x2(blf[nj][0], blf[nj][1], baddr + AREG);
            }
            uint32_t af[4][4];
            uint32_t afl[4][4];
#pragma unroll
            for (int mi = 0; mi < 4; mi++) {
                uint32_t aaddr = abase + (uint32_t)(wm*64 + mi*16 + arow) * ROWB
                               + s*32 + acol;
                ldsm_x4(af[mi][0], af[mi][1], af[mi][2], af[mi][3], aaddr);
                ldsm_x4(afl[mi][0], afl[mi][1], afl[mi][2], afl[mi][3], aaddr + AREG);
            }
#pragma unroll
            for (int mi = 0; mi < 4; mi++)
#pragma unroll
                for (int nj = 0; nj < 4; nj++)
                    mma16816(acc[mi][nj], af[mi], bhf[nj]);   // hi*hi
#pragma unroll
            for (int mi = 0; mi < 4; mi++)
#pragma unroll
                for (int nj = 0; nj < 4; nj++)
                    mma16816(acc[mi][nj], af[mi], blf[nj]);   // hi*lo
#pragma unroll
            for (int mi = 0; mi < 4; mi++)
#pragma unroll
                for (int nj = 0; nj < 4; nj++)
                    mma16816(acc[mi][nj], afl[mi], bhf[nj]);  // lo*hi
        }

        // write prefetched chunk into the other stage
        if (kc + 1 < nchunks) {
            const uint32_t so = (uint32_t)((kc + 1) & 1) * STAGE;
#pragma unroll
            for (int i = 0; i < 4; i++) {
                uint32_t off = so + (uint32_t)(lrow + i * 32) * ROWB + lq * 8;
                *(uint2*)(sm + off)          = sA_h[i];
                *(uint2*)(sm + off + AREG)   = sA_l[i];
                *(uint2*)(sm + off + 2*AREG) = sB_h[i];
                *(uint2*)(sm + off + 3*AREG) = sB_l[i];
            }
        }
        __syncthreads();
    }

    // epilogue
#pragma unroll
    for (int mi = 0; mi < 4; mi++) {
#pragma unroll
        for (int nj = 0; nj < 4; nj++) {
            int r0  = m0 + wm*64 + mi*16 + (lane >> 2);
            int col = n0 + wn*32 + nj*8 + (lane & 3) * 2;
            float2 v01, v23;
            v01.x = acc[mi][nj][0]; v01.y = acc[mi][nj][1];
            v23.x = acc[mi][nj][2]; v23.y = acc[mi][nj][3];
            size_t o0 = (size_t)r0 * N + col;
            size_t o1 = (size_t)(r0 + 8) * N + col;
            if (ADD_RES) {
                float2 q0 = *(const float2*)(R + o0);
                float2 q1 = *(const float2*)(R + o1);
                v01.x += q0.x; v01.y += q0.y;
                v23.x += q1.x; v23.y += q1.y;
            }
            *(float2*)(C + o0) = v01;
            *(float2*)(C + o1) = v23;
        }
    }
}

// ---------------------------------------------------------------------------
// Flash-style attention (fp32 SIMT).
// ---------------------------------------------------------------------------
#define ATTN_SMEM ((64*68 + 64*68 + 64*64) * 4)

__global__ __launch_bounds__(256) void attn_kernel(
    const float* __restrict__ Q, const float* __restrict__ KV,
    float* __restrict__ O)
{
    extern __shared__ float smf[];
    float* Qs = smf;
    float* KP = smf + 64*68;
    float* Vs = KP + 64*68;

    const int qt = blockIdx.x, n = blockIdx.y, b = blockIdx.z;
    const int tid = threadIdx.x;
    const int tx = tid & 15, ty = tid >> 4;
    const int lrow = tid >> 2, lq = tid & 3;

    {
        const float* qb = Q + ((size_t)(qt*64 + lrow) * BB + b) * DM + n * DH;
#pragma unroll
        for (int u = 0; u < 4; u++) {
            int d = u*16 + lq*4;
            float4 v = *(const float4*)(qb + d);
            Qs[(d+0)*68 + lrow] = v.x;
            Qs[(d+1)*68 + lrow] = v.y;
            Qs[(d+2)*68 + lrow] = v.z;
            Qs[(d+3)*68 + lrow] = v.w;
        }
    }

    float o[4][4];
#pragma unroll
    for (int rr = 0; rr < 4; rr++)
#pragma unroll
        for (int cc = 0; cc < 4; cc++) o[rr][cc] = 0.f;
    float mrow[4] = {-1e30f, -1e30f, -1e30f, -1e30f};
    float lacc[4] = {0.f, 0.f, 0.f, 0.f};

    for (int jt = 0; jt < KVL/64; jt++) {
        __syncthreads();
        {
            const float* kb = KV + ((size_t)(jt*64 + lrow) * BB + b) * (2*DM) + n * DH;
#pragma unroll
            for (int u = 0; u < 4; u++) {
                int d = u*16 + lq*4;
                float4 v = *(const float4*)(kb + d);
                KP[(d+0)*68 + lrow] = v.x;
                KP[(d+1)*68 + lrow] = v.y;
                KP[(d+2)*68 + lrow] = v.z;
                KP[(d+3)*68 + lrow] = v.w;
                float4 w = *(const float4*)(kb + DM + d);
                *(float4*)&Vs[lrow*64 + d] = w;
            }
        }
        __syncthreads();

        float s[4][4];
#pragma unroll
        for (int rr = 0; rr < 4; rr++)
#pragma unroll
            for (int cc = 0; cc < 4; cc++) s[rr][cc] = 0.f;
#pragma unroll
        for (int d = 0; d < 64; d++) {
            float a[4], bb[4];
            *(float4*)a  = *(const float4*)&Qs[d*68 + ty*4];
            *(float4*)bb = *(const float4*)&KP[d*68 + tx*4];
#pragma unroll
            for (int rr = 0; rr < 4; rr++)
#pragma unroll
                for (int cc = 0; cc < 4; cc++)
                    s[rr][cc] += a[rr] * bb[cc];
        }

        float p[4][4];
#pragma unroll
        for (int rr = 0; rr < 4; rr++) {
            float rmax = -1e30f;
#pragma unroll
            for (int cc = 0; cc < 4; cc++) {
                s[rr][cc] *= ATTN_SCALE;
                rmax = fmaxf(rmax, s[rr][cc]);
            }
#pragma unroll
            for (int msk = 8; msk; msk >>= 1)
                rmax = fmaxf(rmax, __shfl_xor_sync(0xffffffffu, rmax, msk));
            float mnew = fmaxf(mrow[rr], rmax);
            float fcor = __expf(mrow[rr] - mnew);
            mrow[rr] = mnew;
            float rs = 0.f;
#pragma unroll
            for (int cc = 0; cc < 4; cc++) {
                p[rr][cc] = __expf(s[rr][cc] - mnew);
                rs += p[rr][cc];
            }
#pragma unroll
            for (int msk = 8; msk; msk >>= 1)
                rs += __shfl_xor_sync(0xffffffffu, rs, msk);
            lacc[rr] = lacc[rr] * fcor + rs;
#pragma unroll
            for (int cc = 0; cc < 4; cc++) o[rr][cc] *= fcor;
        }

        __syncthreads();
#pragma unroll
        for (int rr = 0; rr < 4; rr++)
#pragma unroll
            for (int cc = 0; cc < 4; cc++)
                KP[(tx*4+cc)*65 + ty*4+rr] = p[rr][cc];
        __syncthreads();

#pragma unroll 8
        for (int j = 0; j < 64; j++) {
            float4 vb = *(const float4*)&Vs[j*64 + tx*4];
            float a0 = KP[j*65 + ty*4+0];
            float a1 = KP[j*65 + ty*4+1];
            float a2 = KP[j*65 + ty*4+2];
            float a3 = KP[j*65 + ty*4+3];
            o[0][0] += a0*vb.x; o[0][1] += a0*vb.y; o[0][2] += a0*vb.z; o[0][3] += a0*vb.w;
            o[1][0] += a1*vb.x; o[1][1] += a1*vb.y; o[1][2] += a1*vb.z; o[1][3] += a1*vb.w;
            o[2][0] += a2*vb.x; o[2][1] += a2*vb.y; o[2][2] += a2*vb.z; o[2][3] += a2*vb.w;
            o[3][0] += a3*vb.x; o[3][1] += a3*vb.y; o[3][2] += a3*vb.z; o[3][3] += a3*vb.w;
        }
    }

#pragma unroll
    for (int rr = 0; rr < 4; rr++) {
        float inv = 1.f / lacc[rr];
        int gi = qt*64 + ty*4 + rr;
        float4 ov;
        ov.x = o[rr][0]*inv; ov.y = o[rr][1]*inv;
        ov.z = o[rr][2]*inv; ov.w = o[rr][3]*inv;
        *(float4*)(O + ((size_t)gi * BB + b) * DM + n * DH + tx*4) = ov;
    }
}

// ---------------------------------------------------------------------------
// LayerNorm over rows of 1024.
// ---------------------------------------------------------------------------
__global__ __launch_bounds__(256) void ln_kernel(
    const float* __restrict__ Y, const float* __restrict__ gamma,
    const float* __restrict__ beta, float* __restrict__ out)
{
    __shared__ float red1[8];
    __shared__ float red2[8];
    const int row = blockIdx.x, tid = threadIdx.x;
    const float* y = Y + (size_t)row * DM;
    float v[4];
#pragma unroll
    for (int u = 0; u < 4; u++) v[u] = y[tid + u*256];

    float s = v[0] + v[1] + v[2] + v[3];
#pragma unroll
    for (int m = 16; m; m >>= 1) s += __shfl_xor_sync(0xffffffffu, s, m);
    if ((tid & 31) == 0) red1[tid >> 5] = s;
    __syncthreads();
    float tot = 0.f;
#pragma unroll
    for (int w = 0; w < 8; w++) tot += red1[w];
    float mu = tot * (1.f / DM);

    float q = 0.f;
#pragma unroll
    for (int u = 0; u < 4; u++) { float d = v[u] - mu; q += d * d; }
#pragma unroll
    for (int m = 16; m; m >>= 1) q += __shfl_xor_sync(0xffffffffu, q, m);
    if ((tid & 31) == 0) red2[tid >> 5] = q;
    __syncthreads();
    float qtot = 0.f;
#pragma unroll
    for (int w = 0; w < 8; w++) qtot += red2[w];
    float inv = rsqrtf(qtot * (1.f / DM) + 1e-5f);

#pragma unroll
    for (int u = 0; u < 4; u++) {
        int cix = tid + u*256;
        out[(size_t)row * DM + cix] = (v[u] - mu) * inv * gamma[cix] + beta[cix];
    }
}

// ---------------------------------------------------------------------------
extern "C" void kernel_launch(void* const* d_in, const int* in_sizes, int n_in,
                              void* d_out, int out_size)
{
    const float* h     = (const float*)d_in[0];
    const float* c     = (const float*)d_in[1];
    const float* Wq    = (const float*)d_in[2];
    const float* Wkv   = (const float*)d_in[3];
    const float* Wo    = (const float*)d_in[4];
    const float* gamma = (const float*)d_in[5];
    const float* beta  = (const float*)d_in[6];
    float* out = (float*)d_out;

    float *Qb, *KVb, *AVb, *Yb;
    cudaGetSymbolAddress((void**)&Qb,  g_Q);
    cudaGetSymbolAddress((void**)&KVb, g_KV);
    cudaGetSymbolAddress((void**)&AVb, g_AV);
    cudaGetSymbolAddress((void**)&Yb,  g_Y);

    cudaFuncSetAttribute(mma_gemm<false>,
                         cudaFuncAttributeMaxDynamicSharedMemorySize, GEMM_SMEM);
    cudaFuncSetAttribute(mma_gemm<true>,
                         cudaFuncAttributeMaxDynamicSharedMemorySize, GEMM_SMEM);
    cudaFuncSetAttribute(attn_kernel,
                         cudaFuncAttributeMaxDynamicSharedMemorySize, ATTN_SMEM);

    // Q = h @ Wq^T        [4096 x 1024], K=1024
    mma_gemm<false><<<dim3(DM/128, QROWS/128), 256, GEMM_SMEM>>>(
        h, Wq, nullptr, Qb, QROWS, DM, DM);
    // KV = c @ Wkv^T      [8192 x 2048], K=1024
    mma_gemm<false><<<dim3(2*DM/128, KVROWS/128), 256, GEMM_SMEM>>>(
        c, Wkv, nullptr, KVb, KVROWS, 2*DM, DM);
    // attention -> AV     [4096 x 1024]
    attn_kernel<<<dim3(QL/64, NH, BB), 256, ATTN_SMEM>>>(Qb, KVb, AVb);
    // Y = AV @ Wo^T + h   [4096 x 1024]
    mma_gemm<true><<<dim3(DM/128, QROWS/128), 256, GEMM_SMEM>>>(
        AVb, Wo, h, Yb, QROWS, DM, DM);
    // out = LN(Y)
    ln_kernel<<<QROWS, 256>>>(Yb, gamma, beta, out);
}

// round 6
// speedup vs baseline: 1.8910x; 1.5254x over previous
#include <cuda_runtime.h>
#include <cuda_bf16.h>
#include <cstdint>

// ---------------------------------------------------------------------------
// MultiHeadCrossAttn on sm_100 (base target; legacy mma.sync path).
//  Q/KV proj: bf16x3 mma GEMM, epilogue emits pre-split bf16 hi/lo (Q scaled).
//  Attention: mma-based flash attention, bf16x3 for S and PV.
//  O proj:    bf16x3 mma GEMM (fp32 in, fp32 out + residual).
//  LN:        fp32 two-pass.
// ---------------------------------------------------------------------------

#define NH 16
#define DH 64
#define DM 1024
#define QL 1024
#define KVL 2048
#define BB 4
#define QROWS (QL*BB)     // 4096
#define KVROWS (KVL*BB)   // 8192
#define ATTN_SCALE 0.125f

__device__ unsigned short g_Qh [QROWS * DM];        // bf16, prescaled by 0.125
__device__ unsigned short g_Ql [QROWS * DM];
__device__ unsigned short g_KVh[KVROWS * 2 * DM];   // K cols 0-1023, V cols 1024-2047
__device__ unsigned short g_KVl[KVROWS * 2 * DM];
__device__ float g_AV[QROWS * DM];
__device__ float g_Y [QROWS * DM];

// ------------------------------- helpers -----------------------------------
__device__ __forceinline__ uint32_t smem_u32(const void* p) {
    uint32_t a;
    asm("{ .reg .u64 t; cvta.to.shared.u64 t, %1; cvt.u32.u64 %0, t; }"
        : "=r"(a) : "l"(p));
    return a;
}
__device__ __forceinline__ void ldsm_x4(uint32_t& r0, uint32_t& r1,
                                        uint32_t& r2, uint32_t& r3, uint32_t addr) {
    asm volatile("ldmatrix.sync.aligned.m8n8.x4.shared.b16 {%0,%1,%2,%3}, [%4];"
                 : "=r"(r0), "=r"(r1), "=r"(r2), "=r"(r3) : "r"(addr));
}
__device__ __forceinline__ void ldsm_x4t(uint32_t& r0, uint32_t& r1,
                                         uint32_t& r2, uint32_t& r3, uint32_t addr) {
    asm volatile("ldmatrix.sync.aligned.m8n8.x4.trans.shared.b16 {%0,%1,%2,%3}, [%4];"
                 : "=r"(r0), "=r"(r1), "=r"(r2), "=r"(r3) : "r"(addr));
}
__device__ __forceinline__ void ldsm_x2(uint32_t& r0, uint32_t& r1, uint32_t addr) {
    asm volatile("ldmatrix.sync.aligned.m8n8.x2.shared.b16 {%0,%1}, [%2];"
                 : "=r"(r0), "=r"(r1) : "r"(addr));
}
__device__ __forceinline__ void mma16816(float* c, const uint32_t* a, const uint32_t* b) {
    asm volatile("mma.sync.aligned.m16n8k16.row.col.f32.bf16.bf16.f32 "
                 "{%0,%1,%2,%3}, {%4,%5,%6,%7}, {%8,%9}, {%0,%1,%2,%3};"
                 : "+f"(c[0]), "+f"(c[1]), "+f"(c[2]), "+f"(c[3])
                 : "r"(a[0]), "r"(a[1]), "r"(a[2]), "r"(a[3]),
                   "r"(b[0]), "r"(b[1]));
}
// split two fp32 into packed bf16 hi pair + bf16 lo pair
__device__ __forceinline__ void split2(float x, float y, uint32_t& hi, uint32_t& lo) {
    __nv_bfloat16 hx = __float2bfloat16_rn(x);
    __nv_bfloat16 hy = __float2bfloat16_rn(y);
    float lxf = x - __bfloat162float(hx);
    float lyf = y - __bfloat162float(hy);
    __nv_bfloat16 lx = __float2bfloat16_rn(lxf);
    __nv_bfloat16 ly = __float2bfloat16_rn(lyf);
    hi = ((uint32_t)__bfloat16_as_ushort(hy) << 16) | __bfloat16_as_ushort(hx);
    lo = ((uint32_t)__bfloat16_as_ushort(ly) << 16) | __bfloat16_as_ushort(lx);
}
__device__ __forceinline__ void cp16(uint32_t saddr, const void* g) {
    asm volatile("cp.async.cg.shared.global [%0], [%1], 16;"
                 :: "r"(saddr), "l"(g));
}
#define CP_COMMIT() asm volatile("cp.async.commit_group;" ::: "memory")
#define CP_WAIT0()  asm volatile("cp.async.wait_group 0;" ::: "memory")
#define CP_WAIT1()  asm volatile("cp.async.wait_group 1;" ::: "memory")

// ---------------------------------------------------------------------------
// bf16x3 GEMM (NT): C = A[M,K] * B[N,K]^T.
// SPLIT=0: fp32 out + residual.  SPLIT=1: bf16 hi/lo out, scaled.
// CTA 128x128, BK=32, 256 threads, 2-stage smem, register prefetch.
// ---------------------------------------------------------------------------
#define ROWB  80
#define AREG  10240
#define STAGE 40960
#define GEMM_SMEM (2*STAGE)

template<int SPLIT>
__global__ __launch_bounds__(256) void mma_gemm(
    const float* __restrict__ A, const float* __restrict__ Bw,
    const float* __restrict__ R, float* __restrict__ C,
    unsigned short* __restrict__ Ch, unsigned short* __restrict__ Cl,
    float oscale, int M, int N, int K)
{
    extern __shared__ __align__(128) char sm[];
    const uint32_t sb = smem_u32(sm);
    const int tid = threadIdx.x;
    const int wid = tid >> 5, lane = tid & 31;
    const int m0 = blockIdx.y * 128, n0 = blockIdx.x * 128;

    const float* Ag = A  + (size_t)m0 * K;
    const float* Bg = Bw + (size_t)n0 * K;

    const int lrow = tid >> 3;
    const int lq   = tid & 7;
    const int wm = wid & 1, wn = wid >> 1;

    float acc[4][4][4];
#pragma unroll
    for (int mi = 0; mi < 4; mi++)
#pragma unroll
        for (int nj = 0; nj < 4; nj++)
#pragma unroll
            for (int e = 0; e < 4; e++) acc[mi][nj][e] = 0.f;

    const int l8   = lane & 7;
    const int arow = ((lane >> 3) & 1) * 8 + l8;
    const int acol = ((lane >> 4) & 1) * 16;
    const int brow = (lane & 15) & 7;
    const int bcol = (((lane & 15) >> 3) & 1) * 16;

    const int nchunks = K >> 5;
    uint2 sA_h[4], sA_l[4], sB_h[4], sB_l[4];

#pragma unroll
    for (int i = 0; i < 4; i++) {
        int row = lrow + i * 32;
        float4 v = *(const float4*)(Ag + (size_t)row * K + lq * 4);
        split2(v.x, v.y, sA_h[i].x, sA_l[i].x);
        split2(v.z, v.w, sA_h[i].y, sA_l[i].y);
        float4 w = *(const float4*)(Bg + (size_t)row * K + lq * 4);
        split2(w.x, w.y, sB_h[i].x, sB_l[i].x);
        split2(w.z, w.w, sB_h[i].y, sB_l[i].y);
    }
#pragma unroll
    for (int i = 0; i < 4; i++) {
        uint32_t off = (uint32_t)(lrow + i * 32) * ROWB + lq * 8;
        *(uint2*)(sm + off)            = sA_h[i];
        *(uint2*)(sm + off + AREG)     = sA_l[i];
        *(uint2*)(sm + off + 2*AREG)   = sB_h[i];
        *(uint2*)(sm + off + 3*AREG)   = sB_l[i];
    }
    __syncthreads();

    for (int kc = 0; kc < nchunks; kc++) {
        if (kc + 1 < nchunks) {
            const int kk = (kc + 1) << 5;
#pragma unroll
            for (int i = 0; i < 4; i++) {
                int row = lrow + i * 32;
                float4 v = *(const float4*)(Ag + (size_t)row * K + kk + lq * 4);
                split2(v.x, v.y, sA_h[i].x, sA_l[i].x);
                split2(v.z, v.w, sA_h[i].y, sA_l[i].y);
                float4 w = *(const float4*)(Bg + (size_t)row * K + kk + lq * 4);
                split2(w.x, w.y, sB_h[i].x, sB_l[i].x);
                split2(w.z, w.w, sB_h[i].y, sB_l[i].y);
            }
        }
        const uint32_t abase = sb + (uint32_t)(kc & 1) * STAGE;
        const uint32_t bbase = abase + 2 * AREG;
#pragma unroll
        for (int s = 0; s < 2; s++) {
            uint32_t bhf[4][2], blf[4][2];
#pragma unroll
            for (int nj = 0; nj < 4; nj++) {
                uint32_t baddr = bbase + (uint32_t)(wn*32 + nj*8 + brow) * ROWB
                               + s*32 + bcol;
                ldsm_x2(bhf[nj][0], bhf[nj][1], baddr);
                ldsm_x2(blf[nj][0], blf[nj][1], baddr + AREG);
            }
            uint32_t af[4][4], afl[4][4];
#pragma unroll
            for (int mi = 0; mi < 4; mi++) {
                uint32_t aaddr = abase + (uint32_t)(wm*64 + mi*16 + arow) * ROWB
                               + s*32 + acol;
                ldsm_x4(af[mi][0], af[mi][1], af[mi][2], af[mi][3], aaddr);
                ldsm_x4(afl[mi][0], afl[mi][1], afl[mi][2], afl[mi][3], aaddr + AREG);
            }
#pragma unroll
            for (int mi = 0; mi < 4; mi++)
#pragma unroll
                for (int nj = 0; nj < 4; nj++)
                    mma16816(acc[mi][nj], af[mi], bhf[nj]);
#pragma unroll
            for (int mi = 0; mi < 4; mi++)
#pragma unroll
                for (int nj = 0; nj < 4; nj++)
                    mma16816(acc[mi][nj], af[mi], blf[nj]);
#pragma unroll
            for (int mi = 0; mi < 4; mi++)
#pragma unroll
                for (int nj = 0; nj < 4; nj++)
                    mma16816(acc[mi][nj], afl[mi], bhf[nj]);
        }
        if (kc + 1 < nchunks) {
            const uint32_t so = (uint32_t)((kc + 1) & 1) * STAGE;
#pragma unroll
            for (int i = 0; i < 4; i++) {
                uint32_t off = so + (uint32_t)(lrow + i * 32) * ROWB + lq * 8;
                *(uint2*)(sm + off)          = sA_h[i];
                *(uint2*)(sm + off + AREG)   = sA_l[i];
                *(uint2*)(sm + off + 2*AREG) = sB_h[i];
                *(uint2*)(sm + off + 3*AREG) = sB_l[i];
            }
        }
        __syncthreads();
    }

#pragma unroll
    for (int mi = 0; mi < 4; mi++) {
#pragma unroll
        for (int nj = 0; nj < 4; nj++) {
            int r0  = m0 + wm*64 + mi*16 + (lane >> 2);
            int col = n0 + wn*32 + nj*8 + (lane & 3) * 2;
            size_t o0 = (size_t)r0 * N + col;
            size_t o1 = (size_t)(r0 + 8) * N + col;
            if (SPLIT) {
                uint32_t h0, l0, h1, l1;
                split2(acc[mi][nj][0]*oscale, acc[mi][nj][1]*oscale, h0, l0);
                split2(acc[mi][nj][2]*oscale, acc[mi][nj][3]*oscale, h1, l1);
                *(uint32_t*)(Ch + o0) = h0;
                *(uint32_t*)(Cl + o0) = l0;
                *(uint32_t*)(Ch + o1) = h1;
                *(uint32_t*)(Cl + o1) = l1;
            } else {
                float2 v01, v23;
                v01.x = acc[mi][nj][0]; v01.y = acc[mi][nj][1];
                v23.x = acc[mi][nj][2]; v23.y = acc[mi][nj][3];
                float2 q0 = *(const float2*)(R + o0);
                float2 q1 = *(const float2*)(R + o1);
                v01.x += q0.x; v01.y += q0.y;
                v23.x += q1.x; v23.y += q1.y;
                *(float2*)(C + o0) = v01;
                *(float2*)(C + o1) = v23;
            }
        }
    }
}

// ---------------------------------------------------------------------------
// mma flash attention. Block: 128 queries x head x batch, 256 threads (8 warps,
// 16 q-rows each). 32 kv tiles of 64 keys, cp.async double-buffered.
// S = Qh.Kh + Qh.Kl + Ql.Kh ; PV = Ph.Vh + Ph.Vl + Pl.Vh.
// Smem rows: 64 bf16 = 128B + 16 pad = 144B.
// ---------------------------------------------------------------------------
#define AROW 144
#define QH_OFF 0
#define QL_OFF 18432
#define KVBUF_OFF 36864
#define KVBUF_SZ  36864          // Kh 9216 | Kl 9216 | Vh 9216 | Vl 9216
#define ATTN_SMEM (KVBUF_OFF + 2*KVBUF_SZ)   // 110592

__global__ __launch_bounds__(256) void attn_mma(
    const unsigned short* __restrict__ Qh, const unsigned short* __restrict__ Ql,
    const unsigned short* __restrict__ KVh, const unsigned short* __restrict__ KVl,
    float* __restrict__ AV)
{
    extern __shared__ __align__(128) char sm[];
    const uint32_t sb = smem_u32(sm);
    const int qt = blockIdx.x, n = blockIdx.y, b = blockIdx.z;
    const int tid = threadIdx.x;
    const int wid = tid >> 5, lane = tid & 31;

    const int l8   = lane & 7;
    const int arow = ((lane >> 3) & 1) * 8 + l8;
    const int acol = ((lane >> 4) & 1) * 16;
    const int brow = l8;
    const int bcol = (((lane & 15) >> 3) & 1) * 16;

    // ---- async load Q tile (128 x 64, hi+lo) ----
    {
        int c0 = tid * 4;
#pragma unroll
        for (int u = 0; u < 4; u++) {
            int cid = c0 + u;                 // 0..1023
            int row = cid >> 3, c16 = cid & 7;
            size_t grow = (size_t)(qt*128 + row) * BB + b;
            size_t goff = grow * DM + n * DH + c16 * 8;
            cp16(sb + QH_OFF + row*AROW + c16*16, Qh + goff);
            cp16(sb + QL_OFF + row*AROW + c16*16, Ql + goff);
        }
    }
    // ---- async load KV tile 0 into buffer 0 ----
    {
        int c0 = tid * 2;
#pragma unroll
        for (int u = 0; u < 2; u++) {
            int cid = c0 + u;                 // 0..511
            int row = cid >> 3, c16 = cid & 7;
            size_t gr = (size_t)(row) * BB + b;
            size_t ko = gr * (2*DM) + n * DH + c16 * 8;
            size_t vo = ko + DM;
            uint32_t so = sb + KVBUF_OFF + row*AROW + c16*16;
            cp16(so,         KVh + ko);
            cp16(so +  9216, KVl + ko);
            cp16(so + 18432, KVh + vo);
            cp16(so + 27648, KVl + vo);
        }
    }
    CP_COMMIT();

    float o[8][4];
#pragma unroll
    for (int dj = 0; dj < 8; dj++)
#pragma unroll
        for (int e = 0; e < 4; e++) o[dj][e] = 0.f;
    float m0 = -1e30f, m1 = -1e30f, lac0 = 0.f, lac1 = 0.f;

    for (int jt = 0; jt < KVL/64; jt++) {
        if (jt + 1 < KVL/64) {
            uint32_t bufn = sb + KVBUF_OFF + (uint32_t)((jt+1) & 1) * KVBUF_SZ;
            int c0 = tid * 2;
#pragma unroll
            for (int u = 0; u < 2; u++) {
                int cid = c0 + u;
                int row = cid >> 3, c16 = cid & 7;
                size_t gr = (size_t)((jt+1)*64 + row) * BB + b;
                size_t ko = gr * (2*DM) + n * DH + c16 * 8;
                size_t vo = ko + DM;
                uint32_t so = bufn + row*AROW + c16*16;
                cp16(so,         KVh + ko);
                cp16(so +  9216, KVl + ko);
                cp16(so + 18432, KVh + vo);
                cp16(so + 27648, KVl + vo);
            }
            CP_COMMIT();
            CP_WAIT1();
        } else {
            CP_WAIT0();
        }
        __syncthreads();

        const uint32_t kb = sb + KVBUF_OFF + (uint32_t)(jt & 1) * KVBUF_SZ;
        const uint32_t vb = kb + 18432;

        // ---- S = Q K^T  (16 q rows x 64 keys per warp) ----
        float s[8][4];
#pragma unroll
        for (int nj = 0; nj < 8; nj++)
#pragma unroll
            for (int e = 0; e < 4; e++) s[nj][e] = 0.f;

#pragma unroll
        for (int ks = 0; ks < 4; ks++) {
            uint32_t qf[4], qfl[4];
            uint32_t qaddr = sb + QH_OFF + (uint32_t)(wid*16 + arow)*AROW + ks*32 + acol;
            ldsm_x4(qf[0], qf[1], qf[2], qf[3], qaddr);
            ldsm_x4(qfl[0], qfl[1], qfl[2], qfl[3], qaddr + (QL_OFF - QH_OFF));
#pragma unroll
            for (int nj = 0; nj < 8; nj++) {
                uint32_t kh[2], kl[2];
                uint32_t kaddr = kb + (uint32_t)(nj*8 + brow)*AROW + ks*32 + bcol;
                ldsm_x2(kh[0], kh[1], kaddr);
                ldsm_x2(kl[0], kl[1], kaddr + 9216);
                mma16816(s[nj], qf, kh);
                mma16816(s[nj], qf, kl);
                mma16816(s[nj], qfl, kh);
            }
        }

        // ---- online softmax (rows g = lane>>2 and g+8) ----
        float rmax0 = -1e30f, rmax1 = -1e30f;
#pragma unroll
        for (int nj = 0; nj < 8; nj++) {
            rmax0 = fmaxf(rmax0, fmaxf(s[nj][0], s[nj][1]));
            rmax1 = fmaxf(rmax1, fmaxf(s[nj][2], s[nj][3]));
        }
        rmax0 = fmaxf(rmax0, __shfl_xor_sync(0xffffffffu, rmax0, 1));
        rmax0 = fmaxf(rmax0, __shfl_xor_sync(0xffffffffu, rmax0, 2));
        rmax1 = fmaxf(rmax1, __shfl_xor_sync(0xffffffffu, rmax1, 1));
        rmax1 = fmaxf(rmax1, __shfl_xor_sync(0xffffffffu, rmax1, 2));
        float mn0 = fmaxf(m0, rmax0), mn1 = fmaxf(m1, rmax1);
        float fc0 = __expf(m0 - mn0), fc1 = __expf(m1 - mn1);
        m0 = mn0; m1 = mn1;
        float sum0 = 0.f, sum1 = 0.f;
#pragma unroll
        for (int nj = 0; nj < 8; nj++) {
            float p0 = __expf(s[nj][0] - mn0);
            float p1 = __expf(s[nj][1] - mn0);
            float p2 = __expf(s[nj][2] - mn1);
            float p3 = __expf(s[nj][3] - mn1);
            s[nj][0] = p0; s[nj][1] = p1; s[nj][2] = p2; s[nj][3] = p3;
            sum0 += p0 + p1; sum1 += p2 + p3;
        }
        sum0 += __shfl_xor_sync(0xffffffffu, sum0, 1);
        sum0 += __shfl_xor_sync(0xffffffffu, sum0, 2);
        sum1 += __shfl_xor_sync(0xffffffffu, sum1, 1);
        sum1 += __shfl_xor_sync(0xffffffffu, sum1, 2);
        lac0 = lac0 * fc0 + sum0;
        lac1 = lac1 * fc1 + sum1;
#pragma unroll
        for (int dj = 0; dj < 8; dj++) {
            o[dj][0] *= fc0; o[dj][1] *= fc0;
            o[dj][2] *= fc1; o[dj][3] *= fc1;
        }

        // ---- O += P V  (P acc-frags repack directly as A-frags) ----
#pragma unroll
        for (int ks = 0; ks < 4; ks++) {
            uint32_t ah[4], al[4];
            split2(s[2*ks][0],   s[2*ks][1],   ah[0], al[0]);
            split2(s[2*ks][2],   s[2*ks][3],   ah[1], al[1]);
            split2(s[2*ks+1][0], s[2*ks+1][1], ah[2], al[2]);
            split2(s[2*ks+1][2], s[2*ks+1][3], ah[3], al[3]);
#pragma unroll
            for (int djp = 0; djp < 4; djp++) {
                int dj = djp * 2;
                int mm = lane >> 3;
                uint32_t vaddr = vb
                    + (uint32_t)(ks*16 + (mm & 1)*8 + l8) * AROW
                    + (uint32_t)(dj + (mm >> 1)) * 16;
                uint32_t vh[4], vl[4];
                ldsm_x4t(vh[0], vh[1], vh[2], vh[3], vaddr);
                ldsm_x4t(vl[0], vl[1], vl[2], vl[3], vaddr + 9216);
                mma16816(o[dj],   ah, vh);
                mma16816(o[dj+1], ah, vh + 2);
                mma16816(o[dj],   ah, vl);
                mma16816(o[dj+1], ah, vl + 2);
                mma16816(o[dj],   al, vh);
                mma16816(o[dj+1], al, vh + 2);
            }
        }
        __syncthreads();
    }

    // ---- epilogue: divide by l, store fp32 AV ----
    float inv0 = 1.f / lac0, inv1 = 1.f / lac1;
    int g = lane >> 2;
    size_t gr0 = ((size_t)(qt*128 + wid*16 + g)) * BB + b;
    size_t gr1 = gr0 + (size_t)8 * BB;
    int colb = n * DH + (lane & 3) * 2;
#pragma unroll
    for (int dj = 0; dj < 8; dj++) {
        float2 v0, v1;
        v0.x = o[dj][0] * inv0; v0.y = o[dj][1] * inv0;
        v1.x = o[dj][2] * inv1; v1.y = o[dj][3] * inv1;
        *(float2*)(AV + gr0 * DM + colb + dj*8) = v0;
        *(float2*)(AV + gr1 * DM + colb + dj*8) = v1;
    }
}

// ---------------------------------------------------------------------------
// LayerNorm over rows of 1024.
// ---------------------------------------------------------------------------
__global__ __launch_bounds__(256) void ln_kernel(
    const float* __restrict__ Y, const float* __restrict__ gamma,
    const float* __restrict__ beta, float* __restrict__ out)
{
    __shared__ float red1[8];
    __shared__ float red2[8];
    const int row = blockIdx.x, tid = threadIdx.x;
    const float* y = Y + (size_t)row * DM;
    float v[4];
#pragma unroll
    for (int u = 0; u < 4; u++) v[u] = y[tid + u*256];

    float s = v[0] + v[1] + v[2] + v[3];
#pragma unroll
    for (int m = 16; m; m >>= 1) s += __shfl_xor_sync(0xffffffffu, s, m);
    if ((tid & 31) == 0) red1[tid >> 5] = s;
    __syncthreads();
    float tot = 0.f;
#pragma unroll
    for (int w = 0; w < 8; w++) tot += red1[w];
    float mu = tot * (1.f / DM);

    float q = 0.f;
#pragma unroll
    for (int u = 0; u < 4; u++) { float d = v[u] - mu; q += d * d; }
#pragma unroll
    for (int m = 16; m; m >>= 1) q += __shfl_xor_sync(0xffffffffu, q, m);
    if ((tid & 31) == 0) red2[tid >> 5] = q;
    __syncthreads();
    float qtot = 0.f;
#pragma unroll
    for (int w = 0; w < 8; w++) qtot += red2[w];
    float inv = rsqrtf(qtot * (1.f / DM) + 1e-5f);

#pragma unroll
    for (int u = 0; u < 4; u++) {
        int cix = tid + u*256;
        out[(size_t)row * DM + cix] = (v[u] - mu) * inv * gamma[cix] + beta[cix];
    }
}

// ---------------------------------------------------------------------------
extern "C" void kernel_launch(void* const* d_in, const int* in_sizes, int n_in,
                              void* d_out, int out_size)
{
    const float* h     = (const float*)d_in[0];
    const float* c     = (const float*)d_in[1];
    const float* Wq    = (const float*)d_in[2];
    const float* Wkv   = (const float*)d_in[3];
    const float* Wo    = (const float*)d_in[4];
    const float* gamma = (const float*)d_in[5];
    const float* beta  = (const float*)d_in[6];
    float* out = (float*)d_out;

    unsigned short *Qh, *Ql, *KVh, *KVl;
    float *AVb, *Yb;
    cudaGetSymbolAddress((void**)&Qh,  g_Qh);
    cudaGetSymbolAddress((void**)&Ql,  g_Ql);
    cudaGetSymbolAddress((void**)&KVh, g_KVh);
    cudaGetSymbolAddress((void**)&KVl, g_KVl);
    cudaGetSymbolAddress((void**)&AVb, g_AV);
    cudaGetSymbolAddress((void**)&Yb,  g_Y);

    cudaFuncSetAttribute(mma_gemm<0>,
                         cudaFuncAttributeMaxDynamicSharedMemorySize, GEMM_SMEM);
    cudaFuncSetAttribute(mma_gemm<1>,
                         cudaFuncAttributeMaxDynamicSharedMemorySize, GEMM_SMEM);
    cudaFuncSetAttribute(attn_mma,
                         cudaFuncAttributeMaxDynamicSharedMemorySize, ATTN_SMEM);

    // Q = (h @ Wq^T) * ATTN_SCALE -> bf16 hi/lo   [4096 x 1024]
    mma_gemm<1><<<dim3(DM/128, QROWS/128), 256, GEMM_SMEM>>>(
        h, Wq, nullptr, nullptr, Qh, Ql, ATTN_SCALE, QROWS, DM, DM);
    // KV = c @ Wkv^T -> bf16 hi/lo                [8192 x 2048]
    mma_gemm<1><<<dim3(2*DM/128, KVROWS/128), 256, GEMM_SMEM>>>(
        c, Wkv, nullptr, nullptr, KVh, KVl, 1.0f, KVROWS, 2*DM, DM);
    // attention -> AV (fp32)                      [4096 x 1024]
    attn_mma<<<dim3(QL/128, NH, BB), 256, ATTN_SMEM>>>(Qh, Ql, KVh, KVl, AVb);
    // Y = AV @ Wo^T + h                           [4096 x 1024]
    mma_gemm<0><<<dim3(DM/128, QROWS/128), 256, GEMM_SMEM>>>(
        AVb, Wo, h, Yb, nullptr, nullptr, 1.0f, QROWS, DM, DM);
    // out = LN(Y)
    ln_kernel<<<QROWS, 256>>>(Yb, gamma, beta, out);
}

// round 8
// speedup vs baseline: 2.4141x; 1.2766x over previous
#include <cuda_runtime.h>
#include <cuda_bf16.h>
#include <cstdint>

// ---------------------------------------------------------------------------
// MultiHeadCrossAttn on sm_100 (base target; legacy mma.sync path).
//  Pre-split: fp32 -> bf16 hi/lo elementwise (h, c, Wq, Wkv, Wo).
//  GEMMs:     pure-bf16 3-pass mma GEMM, cp.async pipeline, 2 CTA/SM.
//  Attention: mma flash attention (bf16x3), epilogue emits split AV.
//  LN:        fp32 two-pass.
// ---------------------------------------------------------------------------

#define NH 16
#define DH 64
#define DM 1024
#define QL 1024
#define KVL 2048
#define BB 4
#define QROWS (QL*BB)     // 4096
#define KVROWS (KVL*BB)   // 8192
#define ATTN_SCALE 0.125f

typedef unsigned short ushort_t;

// pre-split inputs
__device__ ushort_t g_hh [QROWS * DM];
__device__ ushort_t g_hl [QROWS * DM];
__device__ ushort_t g_ch [KVROWS * DM];
__device__ ushort_t g_cl [KVROWS * DM];
__device__ ushort_t g_Wqh [DM * DM];
__device__ ushort_t g_Wql [DM * DM];
__device__ ushort_t g_Wkvh[2 * DM * DM];
__device__ ushort_t g_Wkvl[2 * DM * DM];
__device__ ushort_t g_Woh [DM * DM];
__device__ ushort_t g_Wol [DM * DM];
// intermediates
__device__ ushort_t g_Qh [QROWS * DM];        // prescaled by 0.125
__device__ ushort_t g_Ql [QROWS * DM];
__device__ ushort_t g_KVh[KVROWS * 2 * DM];   // K cols 0-1023, V cols 1024-2047
__device__ ushort_t g_KVl[KVROWS * 2 * DM];
__device__ ushort_t g_AVh[QROWS * DM];
__device__ ushort_t g_AVl[QROWS * DM];
__device__ float    g_Y  [QROWS * DM];

// ------------------------------- helpers -----------------------------------
__device__ __forceinline__ uint32_t smem_u32(const void* p) {
    uint32_t a;
    asm("{ .reg .u64 t; cvta.to.shared.u64 t, %1; cvt.u32.u64 %0, t; }"
        : "=r"(a) : "l"(p));
    return a;
}
__device__ __forceinline__ void ldsm_x4(uint32_t& r0, uint32_t& r1,
                                        uint32_t& r2, uint32_t& r3, uint32_t addr) {
    asm volatile("ldmatrix.sync.aligned.m8n8.x4.shared.b16 {%0,%1,%2,%3}, [%4];"
                 : "=r"(r0), "=r"(r1), "=r"(r2), "=r"(r3) : "r"(addr));
}
__device__ __forceinline__ void ldsm_x4t(uint32_t& r0, uint32_t& r1,
                                         uint32_t& r2, uint32_t& r3, uint32_t addr) {
    asm volatile("ldmatrix.sync.aligned.m8n8.x4.trans.shared.b16 {%0,%1,%2,%3}, [%4];"
                 : "=r"(r0), "=r"(r1), "=r"(r2), "=r"(r3) : "r"(addr));
}
__device__ __forceinline__ void ldsm_x2(uint32_t& r0, uint32_t& r1, uint32_t addr) {
    asm volatile("ldmatrix.sync.aligned.m8n8.x2.shared.b16 {%0,%1}, [%2];"
                 : "=r"(r0), "=r"(r1) : "r"(addr));
}
__device__ __forceinline__ void mma16816(float* c, const uint32_t* a, const uint32_t* b) {
    asm volatile("mma.sync.aligned.m16n8k16.row.col.f32.bf16.bf16.f32 "
                 "{%0,%1,%2,%3}, {%4,%5,%6,%7}, {%8,%9}, {%0,%1,%2,%3};"
                 : "+f"(c[0]), "+f"(c[1]), "+f"(c[2]), "+f"(c[3])
                 : "r"(a[0]), "r"(a[1]), "r"(a[2]), "r"(a[3]),
                   "r"(b[0]), "r"(b[1]));
}
__device__ __forceinline__ void split2(float x, float y, uint32_t& hi, uint32_t& lo) {
    __nv_bfloat16 hx = __float2bfloat16_rn(x);
    __nv_bfloat16 hy = __float2bfloat16_rn(y);
    float lxf = x - __bfloat162float(hx);
    float lyf = y - __bfloat162float(hy);
    __nv_bfloat16 lx = __float2bfloat16_rn(lxf);
    __nv_bfloat16 ly = __float2bfloat16_rn(lyf);
    hi = ((uint32_t)__bfloat16_as_ushort(hy) << 16) | __bfloat16_as_ushort(hx);
    lo = ((uint32_t)__bfloat16_as_ushort(ly) << 16) | __bfloat16_as_ushort(lx);
}
__device__ __forceinline__ void cp16(uint32_t saddr, const void* g) {
    asm volatile("cp.async.cg.shared.global [%0], [%1], 16;"
                 :: "r"(saddr), "l"(g));
}
#define CP_COMMIT() asm volatile("cp.async.commit_group;" ::: "memory")
#define CP_WAIT0()  asm volatile("cp.async.wait_group 0;" ::: "memory")
#define CP_WAIT1()  asm volatile("cp.async.wait_group 1;" ::: "memory")

// ---------------------------------------------------------------------------
// split: fp32 -> bf16 hi/lo
// ---------------------------------------------------------------------------
__global__ __launch_bounds__(256) void split_kernel(
    const float* __restrict__ X, ushort_t* __restrict__ Xh,
    ushort_t* __restrict__ Xl, int n)
{
    int idx = (blockIdx.x * 256 + threadIdx.x) * 4;
    if (idx >= n) return;
    float4 v = *(const float4*)(X + idx);
    uint32_t h0, l0, h1, l1;
    split2(v.x, v.y, h0, l0);
    split2(v.z, v.w, h1, l1);
    uint2 hv; hv.x = h0; hv.y = h1;
    uint2 lv; lv.x = l0; lv.y = l1;
    *(uint2*)(Xh + idx) = hv;
    *(uint2*)(Xl + idx) = lv;
}

// ---------------------------------------------------------------------------
// Pure-bf16 3-pass GEMM (NT): C = A[M,K] * B[N,K]^T, A/B pre-split hi/lo.
// CTA 128x128, BK=32, 256 threads (8 warps, warp tile 64x32),
// 2-stage cp.async pipeline. Smem rows: 32 bf16 = 64B + 16 pad = 80B.
// SPLIT=1: outputs bf16 hi/lo (scaled). SPLIT=0: fp32 + residual.
// ---------------------------------------------------------------------------
#define ROWB  80
#define AREG  10240              // 128 rows * 80B
#define STAGE 40960              // Ah | Al | Bh | Bl
#define GEMM_SMEM (2*STAGE)      // 81920

template<int SPLIT>
__global__ __launch_bounds__(256, 2) void mma_gemm(
    const ushort_t* __restrict__ Ah_g, const ushort_t* __restrict__ Al_g,
    const ushort_t* __restrict__ Bh_g, const ushort_t* __restrict__ Bl_g,
    const float* __restrict__ R, float* __restrict__ C,
    ushort_t* __restrict__ Ch, ushort_t* __restrict__ Cl,
    float oscale, int M, int N, int K)
{
    extern __shared__ __align__(128) char sm[];
    const uint32_t sb = smem_u32(sm);
    const int tid = threadIdx.x;
    const int wid = tid >> 5, lane = tid & 31;
    const int m0 = blockIdx.y * 128, n0 = blockIdx.x * 128;
    const int wm = wid & 1, wn = wid >> 1;

    // stage-fill indices: 512 x 16B chunks per array, 2 per thread
    const int cid0 = tid * 2;

    float acc[4][4][4];
#pragma unroll
    for (int mi = 0; mi < 4; mi++)
#pragma unroll
        for (int nj = 0; nj < 4; nj++)
#pragma unroll
            for (int e = 0; e < 4; e++) acc[mi][nj][e] = 0.f;

    const int l8   = lane & 7;
    const int arow = ((lane >> 3) & 1) * 8 + l8;
    const int acol = ((lane >> 4) & 1) * 16;
    const int brow = (lane & 15) & 7;
    const int bcol = (((lane & 15) >> 3) & 1) * 16;

    const int nchunks = K >> 5;

    // issue stage kc into buffer kc&1
    auto issue = [&](int kc) {
        const int kk = kc << 5;
        const uint32_t sbase = sb + (uint32_t)(kc & 1) * STAGE;
#pragma unroll
        for (int u = 0; u < 2; u++) {
            int cid = cid0 + u;              // 0..511
            int row = cid >> 2, c16 = cid & 3;
            uint32_t so = sbase + (uint32_t)row * ROWB + c16 * 16;
            size_t ao = (size_t)(m0 + row) * K + kk + c16 * 8;
            size_t bo = (size_t)(n0 + row) * K + kk + c16 * 8;
            cp16(so,          Ah_g + ao);
            cp16(so +   AREG, Al_g + ao);
            cp16(so + 2*AREG, Bh_g + bo);
            cp16(so + 3*AREG, Bl_g + bo);
        }
        CP_COMMIT();
    };

    issue(0);

    for (int kc = 0; kc < nchunks; kc++) {
        if (kc + 1 < nchunks) { issue(kc + 1); CP_WAIT1(); }
        else                  { CP_WAIT0(); }
        __syncthreads();

        const uint32_t abase = sb + (uint32_t)(kc & 1) * STAGE;
        const uint32_t bbase = abase + 2 * AREG;
#pragma unroll
        for (int s = 0; s < 2; s++) {
            uint32_t bhf[4][2], blf[4][2];
#pragma unroll
            for (int nj = 0; nj < 4; nj++) {
                uint32_t baddr = bbase + (uint32_t)(wn*32 + nj*8 + brow) * ROWB
                               + s*32 + bcol;
                ldsm_x2(bhf[nj][0], bhf[nj][1], baddr);
                ldsm_x2(blf[nj][0], blf[nj][1], baddr + AREG);
            }
            uint32_t af[4][4], afl[4][4];
#pragma unroll
            for (int mi = 0; mi < 4; mi++) {
                uint32_t aaddr = abase + (uint32_t)(wm*64 + mi*16 + arow) * ROWB
                               + s*32 + acol;
                ldsm_x4(af[mi][0], af[mi][1], af[mi][2], af[mi][3], aaddr);
                ldsm_x4(afl[mi][0], afl[mi][1], afl[mi][2], afl[mi][3], aaddr + AREG);
            }
#pragma unroll
            for (int mi = 0; mi < 4; mi++)
#pragma unroll
                for (int nj = 0; nj < 4; nj++)
                    mma16816(acc[mi][nj], af[mi], bhf[nj]);   // hi*hi
#pragma unroll
            for (int mi = 0; mi < 4; mi++)
#pragma unroll
                for (int nj = 0; nj < 4; nj++)
                    mma16816(acc[mi][nj], af[mi], blf[nj]);   // hi*lo
#pragma unroll
            for (int mi = 0; mi < 4; mi++)
#pragma unroll
                for (int nj = 0; nj < 4; nj++)
                    mma16816(acc[mi][nj], afl[mi], bhf[nj]);  // lo*hi
        }
        __syncthreads();
    }

#pragma unroll
    for (int mi = 0; mi < 4; mi++) {
#pragma unroll
        for (int nj = 0; nj < 4; nj++) {
            int r0  = m0 + wm*64 + mi*16 + (lane >> 2);
            int col = n0 + wn*32 + nj*8 + (lane & 3) * 2;
            size_t o0 = (size_t)r0 * N + col;
            size_t o1 = (size_t)(r0 + 8) * N + col;
            if (SPLIT) {
                uint32_t h0, l0, h1, l1;
                split2(acc[mi][nj][0]*oscale, acc[mi][nj][1]*oscale, h0, l0);
                split2(acc[mi][nj][2]*oscale, acc[mi][nj][3]*oscale, h1, l1);
                *(uint32_t*)(Ch + o0) = h0;
                *(uint32_t*)(Cl + o0) = l0;
                *(uint32_t*)(Ch + o1) = h1;
                *(uint32_t*)(Cl + o1) = l1;
            } else {
                float2 v01, v23;
                v01.x = acc[mi][nj][0]; v01.y = acc[mi][nj][1];
                v23.x = acc[mi][nj][2]; v23.y = acc[mi][nj][3];
                float2 q0 = *(const float2*)(R + o0);
                float2 q1 = *(const float2*)(R + o1);
                v01.x += q0.x; v01.y += q0.y;
                v23.x += q1.x; v23.y += q1.y;
                *(float2*)(C + o0) = v01;
                *(float2*)(C + o1) = v23;
            }
        }
    }
}

// ---------------------------------------------------------------------------
// mma flash attention. Block: 128 queries x head x batch, 256 threads (8 warps,
// 16 q-rows each). 32 kv tiles of 64 keys, cp.async double-buffered.
// S = Qh.Kh + Qh.Kl + Ql.Kh ; PV = Ph.Vh + Ph.Vl + Pl.Vh.
// Epilogue writes split bf16 AV.
// ---------------------------------------------------------------------------
#define AROW 144
#define QH_OFF 0
#define QL_OFF 18432
#define KVBUF_OFF 36864
#define KVBUF_SZ  36864
#define ATTN_SMEM (KVBUF_OFF + 2*KVBUF_SZ)   // 110592

__global__ __launch_bounds__(256) void attn_mma(
    const ushort_t* __restrict__ Qh, const ushort_t* __restrict__ Ql,
    const ushort_t* __restrict__ KVh, const ushort_t* __restrict__ KVl,
    ushort_t* __restrict__ AVh, ushort_t* __restrict__ AVl)
{
    extern __shared__ __align__(128) char sm[];
    const uint32_t sb = smem_u32(sm);
    const int qt = blockIdx.x, n = blockIdx.y, b = blockIdx.z;
    const int tid = threadIdx.x;
    const int wid = tid >> 5, lane = tid & 31;

    const int l8   = lane & 7;
    const int arow = ((lane >> 3) & 1) * 8 + l8;
    const int acol = ((lane >> 4) & 1) * 16;
    const int brow = l8;
    const int bcol = (((lane & 15) >> 3) & 1) * 16;

    {
        int c0 = tid * 4;
#pragma unroll
        for (int u = 0; u < 4; u++) {
            int cid = c0 + u;
            int row = cid >> 3, c16 = cid & 7;
            size_t grow = (size_t)(qt*128 + row) * BB + b;
            size_t goff = grow * DM + n * DH + c16 * 8;
            cp16(sb + QH_OFF + row*AROW + c16*16, Qh + goff);
            cp16(sb + QL_OFF + row*AROW + c16*16, Ql + goff);
        }
    }
    {
        int c0 = tid * 2;
#pragma unroll
        for (int u = 0; u < 2; u++) {
            int cid = c0 + u;
            int row = cid >> 3, c16 = cid & 7;
            size_t gr = (size_t)(row) * BB + b;
            size_t ko = gr * (2*DM) + n * DH + c16 * 8;
            size_t vo = ko + DM;
            uint32_t so = sb + KVBUF_OFF + row*AROW + c16*16;
            cp16(so,         KVh + ko);
            cp16(so +  9216, KVl + ko);
            cp16(so + 18432, KVh + vo);
            cp16(so + 27648, KVl + vo);
        }
    }
    CP_COMMIT();

    float o[8][4];
#pragma unroll
    for (int dj = 0; dj < 8; dj++)
#pragma unroll
        for (int e = 0; e < 4; e++) o[dj][e] = 0.f;
    float m0 = -1e30f, m1 = -1e30f, lac0 = 0.f, lac1 = 0.f;

    for (int jt = 0; jt < KVL/64; jt++) {
        if (jt + 1 < KVL/64) {
            uint32_t bufn = sb + KVBUF_OFF + (uint32_t)((jt+1) & 1) * KVBUF_SZ;
            int c0 = tid * 2;
#pragma unroll
            for (int u = 0; u < 2; u++) {
                int cid = c0 + u;
                int row = cid >> 3, c16 = cid & 7;
                size_t gr = (size_t)((jt+1)*64 + row) * BB + b;
                size_t ko = gr * (2*DM) + n * DH + c16 * 8;
                size_t vo = ko + DM;
                uint32_t so = bufn + row*AROW + c16*16;
                cp16(so,         KVh + ko);
                cp16(so +  9216, KVl + ko);
                cp16(so + 18432, KVh + vo);
                cp16(so + 27648, KVl + vo);
            }
            CP_COMMIT();
            CP_WAIT1();
        } else {
            CP_WAIT0();
        }
        __syncthreads();

        const uint32_t kb = sb + KVBUF_OFF + (uint32_t)(jt & 1) * KVBUF_SZ;
        const uint32_t vb = kb + 18432;

        float s[8][4];
#pragma unroll
        for (int nj = 0; nj < 8; nj++)
#pragma unroll
            for (int e = 0; e < 4; e++) s[nj][e] = 0.f;

#pragma unroll
        for (int ks = 0; ks < 4; ks++) {
            uint32_t qf[4], qfl[4];
            uint32_t qaddr = sb + QH_OFF + (uint32_t)(wid*16 + arow)*AROW + ks*32 + acol;
            ldsm_x4(qf[0], qf[1], qf[2], qf[3], qaddr);
            ldsm_x4(qfl[0], qfl[1], qfl[2], qfl[3], qaddr + (QL_OFF - QH_OFF));
#pragma unroll
            for (int nj = 0; nj < 8; nj++) {
                uint32_t kh[2], kl[2];
                uint32_t kaddr = kb + (uint32_t)(nj*8 + brow)*AROW + ks*32 + bcol;
                ldsm_x2(kh[0], kh[1], kaddr);
                ldsm_x2(kl[0], kl[1], kaddr + 9216);
                mma16816(s[nj], qf, kh);
                mma16816(s[nj], qf, kl);
                mma16816(s[nj], qfl, kh);
            }
        }

        float rmax0 = -1e30f, rmax1 = -1e30f;
#pragma unroll
        for (int nj = 0; nj < 8; nj++) {
            rmax0 = fmaxf(rmax0, fmaxf(s[nj][0], s[nj][1]));
            rmax1 = fmaxf(rmax1, fmaxf(s[nj][2], s[nj][3]));
        }
        rmax0 = fmaxf(rmax0, __shfl_xor_sync(0xffffffffu, rmax0, 1));
        rmax0 = fmaxf(rmax0, __shfl_xor_sync(0xffffffffu, rmax0, 2));
        rmax1 = fmaxf(rmax1, __shfl_xor_sync(0xffffffffu, rmax1, 1));
        rmax1 = fmaxf(rmax1, __shfl_xor_sync(0xffffffffu, rmax1, 2));
        float mn0 = fmaxf(m0, rmax0), mn1 = fmaxf(m1, rmax1);
        float fc0 = __expf(m0 - mn0), fc1 = __expf(m1 - mn1);
        m0 = mn0; m1 = mn1;
        float sum0 = 0.f, sum1 = 0.f;
#pragma unroll
        for (int nj = 0; nj < 8; nj++) {
            float p0 = __expf(s[nj][0] - mn0);
            float p1 = __expf(s[nj][1] - mn0);
            float p2 = __expf(s[nj][2] - mn1);
            float p3 = __expf(s[nj][3] - mn1);
            s[nj][0] = p0; s[nj][1] = p1; s[nj][2] = p2; s[nj][3] = p3;
            sum0 += p0 + p1; sum1 += p2 + p3;
        }
        sum0 += __shfl_xor_sync(0xffffffffu, sum0, 1);
        sum0 += __shfl_xor_sync(0xffffffffu, sum0, 2);
        sum1 += __shfl_xor_sync(0xffffffffu, sum1, 1);
        sum1 += __shfl_xor_sync(0xffffffffu, sum1, 2);
        lac0 = lac0 * fc0 + sum0;
        lac1 = lac1 * fc1 + sum1;
#pragma unroll
        for (int dj = 0; dj < 8; dj++) {
            o[dj][0] *= fc0; o[dj][1] *= fc0;
            o[dj][2] *= fc1; o[dj][3] *= fc1;
        }

#pragma unroll
        for (int ks = 0; ks < 4; ks++) {
            uint32_t ah[4], al[4];
            split2(s[2*ks][0],   s[2*ks][1],   ah[0], al[0]);
            split2(s[2*ks][2],   s[2*ks][3],   ah[1], al[1]);
            split2(s[2*ks+1][0], s[2*ks+1][1], ah[2], al[2]);
            split2(s[2*ks+1][2], s[2*ks+1][3], ah[3], al[3]);
#pragma unroll
            for (int djp = 0; djp < 4; djp++) {
                int dj = djp * 2;
                int mm = lane >> 3;
                uint32_t vaddr = vb
                    + (uint32_t)(ks*16 + (mm & 1)*8 + l8) * AROW
                    + (uint32_t)(dj + (mm >> 1)) * 16;
                uint32_t vh[4], vl[4];
                ldsm_x4t(vh[0], vh[1], vh[2], vh[3], vaddr);
                ldsm_x4t(vl[0], vl[1], vl[2], vl[3], vaddr + 9216);
                mma16816(o[dj],   ah, vh);
                mma16816(o[dj+1], ah, vh + 2);
                mma16816(o[dj],   ah, vl);
                mma16816(o[dj+1], ah, vl + 2);
                mma16816(o[dj],   al, vh);
                mma16816(o[dj+1], al, vh + 2);
            }
        }
        __syncthreads();
    }

    // ---- epilogue: divide by l, split to bf16 hi/lo ----
    float inv0 = 1.f / lac0, inv1 = 1.f / lac1;
    int g = lane >> 2;
    size_t gr0 = ((size_t)(qt*128 + wid*16 + g)) * BB + b;
    size_t gr1 = gr0 + (size_t)8 * BB;
    int colb = n * DH + (lane & 3) * 2;
#pragma unroll
    for (int dj = 0; dj < 8; dj++) {
        uint32_t h0, l0, h1, l1;
        split2(o[dj][0] * inv0, o[dj][1] * inv0, h0, l0);
        split2(o[dj][2] * inv1, o[dj][3] * inv1, h1, l1);
        *(uint32_t*)(AVh + gr0 * DM + colb + dj*8) = h0;
        *(uint32_t*)(AVl + gr0 * DM + colb + dj*8) = l0;
        *(uint32_t*)(AVh + gr1 * DM + colb + dj*8) = h1;
        *(uint32_t*)(AVl + gr1 * DM + colb + dj*8) = l1;
    }
}

// ---------------------------------------------------------------------------
// LayerNorm over rows of 1024.
// ---------------------------------------------------------------------------
__global__ __launch_bounds__(256) void ln_kernel(
    const float* __restrict__ Y, const float* __restrict__ gamma,
    const float* __restrict__ beta, float* __restrict__ out)
{
    __shared__ float red1[8];
    __shared__ float red2[8];
    const int row = blockIdx.x, tid = threadIdx.x;
    const float* y = Y + (size_t)row * DM;
    float v[4];
#pragma unroll
    for (int u = 0; u < 4; u++) v[u] = y[tid + u*256];

    float s = v[0] + v[1] + v[2] + v[3];
#pragma unroll
    for (int m = 16; m; m >>= 1) s += __shfl_xor_sync(0xffffffffu, s, m);
    if ((tid & 31) == 0) red1[tid >> 5] = s;
    __syncthreads();
    float tot = 0.f;
#pragma unroll
    for (int w = 0; w < 8; w++) tot += red1[w];
    float mu = tot * (1.f / DM);

    float q = 0.f;
#pragma unroll
    for (int u = 0; u < 4; u++) { float d = v[u] - mu; q += d * d; }
#pragma unroll
    for (int m = 16; m; m >>= 1) q += __shfl_xor_sync(0xffffffffu, q, m);
    if ((tid & 31) == 0) red2[tid >> 5] = q;
    __syncthreads();
    float qtot = 0.f;
#pragma unroll
    for (int w = 0; w < 8; w++) qtot += red2[w];
    float inv = rsqrtf(qtot * (1.f / DM) + 1e-5f);

#pragma unroll
    for (int u = 0; u < 4; u++) {
        int cix = tid + u*256;
        out[(size_t)row * DM + cix] = (v[u] - mu) * inv * gamma[cix] + beta[cix];
    }
}

// ---------------------------------------------------------------------------
extern "C" void kernel_launch(void* const* d_in, const int* in_sizes, int n_in,
                              void* d_out, int out_size)
{
    const float* h     = (const float*)d_in[0];
    const float* c     = (const float*)d_in[1];
    const float* Wq    = (const float*)d_in[2];
    const float* Wkv   = (const float*)d_in[3];
    const float* Wo    = (const float*)d_in[4];
    const float* gamma = (const float*)d_in[5];
    const float* beta  = (const float*)d_in[6];
    float* out = (float*)d_out;

    ushort_t *hh, *hl, *ch, *cl, *Wqh, *Wql, *Wkvh, *Wkvl, *Woh, *Wol;
    ushort_t *Qh, *Ql, *KVh, *KVl, *AVh, *AVl;
    float *Yb;
    cudaGetSymbolAddress((void**)&hh,   g_hh);
    cudaGetSymbolAddress((void**)&hl,   g_hl);
    cudaGetSymbolAddress((void**)&ch,   g_ch);
    cudaGetSymbolAddress((void**)&cl,   g_cl);
    cudaGetSymbolAddress((void**)&Wqh,  g_Wqh);
    cudaGetSymbolAddress((void**)&Wql,  g_Wql);
    cudaGetSymbolAddress((void**)&Wkvh, g_Wkvh);
    cudaGetSymbolAddress((void**)&Wkvl, g_Wkvl);
    cudaGetSymbolAddress((void**)&Woh,  g_Woh);
    cudaGetSymbolAddress((void**)&Wol,  g_Wol);
    cudaGetSymbolAddress((void**)&Qh,   g_Qh);
    cudaGetSymbolAddress((void**)&Ql,   g_Ql);
    cudaGetSymbolAddress((void**)&KVh,  g_KVh);
    cudaGetSymbolAddress((void**)&KVl,  g_KVl);
    cudaGetSymbolAddress((void**)&AVh,  g_AVh);
    cudaGetSymbolAddress((void**)&AVl,  g_AVl);
    cudaGetSymbolAddress((void**)&Yb,   g_Y);

    cudaFuncSetAttribute(mma_gemm<0>,
                         cudaFuncAttributeMaxDynamicSharedMemorySize, GEMM_SMEM);
    cudaFuncSetAttribute(mma_gemm<1>,
                         cudaFuncAttributeMaxDynamicSharedMemorySize, GEMM_SMEM);
    cudaFuncSetAttribute(attn_mma,
                         cudaFuncAttributeMaxDynamicSharedMemorySize, ATTN_SMEM);

    // ---- pre-split all fp32 inputs into bf16 hi/lo ----
    split_kernel<<<QROWS*DM/1024, 256>>>(h,   hh,   hl,   QROWS*DM);
    split_kernel<<<KVROWS*DM/1024, 256>>>(c,  ch,   cl,   KVROWS*DM);
    split_kernel<<<DM*DM/1024, 256>>>(Wq,     Wqh,  Wql,  DM*DM);
    split_kernel<<<2*DM*DM/1024, 256>>>(Wkv,  Wkvh, Wkvl, 2*DM*DM);
    split_kernel<<<DM*DM/1024, 256>>>(Wo,     Woh,  Wol,  DM*DM);

    // Q = (h @ Wq^T) * ATTN_SCALE -> bf16 hi/lo   [4096 x 1024]
    mma_gemm<1><<<dim3(DM/128, QROWS/128), 256, GEMM_SMEM>>>(
        hh, hl, Wqh, Wql, nullptr, nullptr, Qh, Ql, ATTN_SCALE, QROWS, DM, DM);
    // KV = c @ Wkv^T -> bf16 hi/lo                [8192 x 2048]
    mma_gemm<1><<<dim3(2*DM/128, KVROWS/128), 256, GEMM_SMEM>>>(
        ch, cl, Wkvh, Wkvl, nullptr, nullptr, KVh, KVl, 1.0f, KVROWS, 2*DM, DM);
    // attention -> AV split                       [4096 x 1024]
    attn_mma<<<dim3(QL/128, NH, BB), 256, ATTN_SMEM>>>(Qh, Ql, KVh, KVl, AVh, AVl);
    // Y = AV @ Wo^T + h                           [4096 x 1024]
    mma_gemm<0><<<dim3(DM/128, QROWS/128), 256, GEMM_SMEM>>>(
        AVh, AVl, Woh, Wol, h, Yb, nullptr, nullptr, 1.0f, QROWS, DM, DM);
    // out = LN(Y)
    ln_kernel<<<QROWS, 256>>>(Yb, gamma, beta, out);
}

// round 9
// speedup vs baseline: 2.4356x; 1.0089x over previous
#include <cuda_runtime.h>
#include <cuda_bf16.h>
#include <cstdint>

// ---------------------------------------------------------------------------
// MultiHeadCrossAttn on sm_100 (base target; legacy mma.sync path).
//  Pre-split: fp32 -> bf16 hi/lo elementwise (h, c, Wq, Wkv, Wo).
//  GEMMs:     pure-bf16 3-pass mma GEMM, cp.async pipeline, 2 CTA/SM, x4 B-LDSM.
//  Attention: mma flash attention (bf16x3), 2 CTA/SM, x4 K-LDSM.
//  LN:        fp32 two-pass.
// ---------------------------------------------------------------------------

#define NH 16
#define DH 64
#define DM 1024
#define QL 1024
#define KVL 2048
#define BB 4
#define QROWS (QL*BB)     // 4096
#define KVROWS (KVL*BB)   // 8192
#define ATTN_SCALE 0.125f

typedef unsigned short ushort_t;

// pre-split inputs
__device__ ushort_t g_hh [QROWS * DM];
__device__ ushort_t g_hl [QROWS * DM];
__device__ ushort_t g_ch [KVROWS * DM];
__device__ ushort_t g_cl [KVROWS * DM];
__device__ ushort_t g_Wqh [DM * DM];
__device__ ushort_t g_Wql [DM * DM];
__device__ ushort_t g_Wkvh[2 * DM * DM];
__device__ ushort_t g_Wkvl[2 * DM * DM];
__device__ ushort_t g_Woh [DM * DM];
__device__ ushort_t g_Wol [DM * DM];
// intermediates
__device__ ushort_t g_Qh [QROWS * DM];        // prescaled by 0.125
__device__ ushort_t g_Ql [QROWS * DM];
__device__ ushort_t g_KVh[KVROWS * 2 * DM];   // K cols 0-1023, V cols 1024-2047
__device__ ushort_t g_KVl[KVROWS * 2 * DM];
__device__ ushort_t g_AVh[QROWS * DM];
__device__ ushort_t g_AVl[QROWS * DM];
__device__ float    g_Y  [QROWS * DM];

// ------------------------------- helpers -----------------------------------
__device__ __forceinline__ uint32_t smem_u32(const void* p) {
    uint32_t a;
    asm("{ .reg .u64 t; cvta.to.shared.u64 t, %1; cvt.u32.u64 %0, t; }"
        : "=r"(a) : "l"(p));
    return a;
}
__device__ __forceinline__ void ldsm_x4(uint32_t& r0, uint32_t& r1,
                                        uint32_t& r2, uint32_t& r3, uint32_t addr) {
    asm volatile("ldmatrix.sync.aligned.m8n8.x4.shared.b16 {%0,%1,%2,%3}, [%4];"
                 : "=r"(r0), "=r"(r1), "=r"(r2), "=r"(r3) : "r"(addr));
}
__device__ __forceinline__ void ldsm_x4t(uint32_t& r0, uint32_t& r1,
                                         uint32_t& r2, uint32_t& r3, uint32_t addr) {
    asm volatile("ldmatrix.sync.aligned.m8n8.x4.trans.shared.b16 {%0,%1,%2,%3}, [%4];"
                 : "=r"(r0), "=r"(r1), "=r"(r2), "=r"(r3) : "r"(addr));
}
__device__ __forceinline__ void mma16816(float* c, const uint32_t* a, const uint32_t* b) {
    asm volatile("mma.sync.aligned.m16n8k16.row.col.f32.bf16.bf16.f32 "
                 "{%0,%1,%2,%3}, {%4,%5,%6,%7}, {%8,%9}, {%0,%1,%2,%3};"
                 : "+f"(c[0]), "+f"(c[1]), "+f"(c[2]), "+f"(c[3])
                 : "r"(a[0]), "r"(a[1]), "r"(a[2]), "r"(a[3]),
                   "r"(b[0]), "r"(b[1]));
}
__device__ __forceinline__ void split2(float x, float y, uint32_t& hi, uint32_t& lo) {
    __nv_bfloat16 hx = __float2bfloat16_rn(x);
    __nv_bfloat16 hy = __float2bfloat16_rn(y);
    float lxf = x - __bfloat162float(hx);
    float lyf = y - __bfloat162float(hy);
    __nv_bfloat16 lx = __float2bfloat16_rn(lxf);
    __nv_bfloat16 ly = __float2bfloat16_rn(lyf);
    hi = ((uint32_t)__bfloat16_as_ushort(hy) << 16) | __bfloat16_as_ushort(hx);
    lo = ((uint32_t)__bfloat16_as_ushort(ly) << 16) | __bfloat16_as_ushort(lx);
}
__device__ __forceinline__ void cp16(uint32_t saddr, const void* g) {
    asm volatile("cp.async.cg.shared.global [%0], [%1], 16;"
                 :: "r"(saddr), "l"(g));
}
#define CP_COMMIT() asm volatile("cp.async.commit_group;" ::: "memory")
#define CP_WAIT0()  asm volatile("cp.async.wait_group 0;" ::: "memory")
#define CP_WAIT1()  asm volatile("cp.async.wait_group 1;" ::: "memory")

// ---------------------------------------------------------------------------
// split: fp32 -> bf16 hi/lo
// ---------------------------------------------------------------------------
__global__ __launch_bounds__(256) void split_kernel(
    const float* __restrict__ X, ushort_t* __restrict__ Xh,
    ushort_t* __restrict__ Xl, int n)
{
    int idx = (blockIdx.x * 256 + threadIdx.x) * 4;
    if (idx >= n) return;
    float4 v = *(const float4*)(X + idx);
    uint32_t h0, l0, h1, l1;
    split2(v.x, v.y, h0, l0);
    split2(v.z, v.w, h1, l1);
    uint2 hv; hv.x = h0; hv.y = h1;
    uint2 lv; lv.x = l0; lv.y = l1;
    *(uint2*)(Xh + idx) = hv;
    *(uint2*)(Xl + idx) = lv;
}

// ---------------------------------------------------------------------------
// Pure-bf16 3-pass GEMM (NT): C = A[M,K] * B[N,K]^T, A/B pre-split hi/lo.
// CTA 128x128, BK=32, 256 threads (8 warps, warp tile 64x32),
// 2-stage cp.async pipeline. Smem rows: 32 bf16 = 64B + 16 pad = 80B.
// B fragments loaded as x4 (two n-tiles per LDSM).
// SPLIT=1: outputs bf16 hi/lo (scaled). SPLIT=0: fp32 + residual.
// ---------------------------------------------------------------------------
#define ROWB  80
#define AREG  10240              // 128 rows * 80B
#define STAGE 40960              // Ah | Al | Bh | Bl
#define GEMM_SMEM (2*STAGE)      // 81920

template<int SPLIT>
__global__ __launch_bounds__(256, 2) void mma_gemm(
    const ushort_t* __restrict__ Ah_g, const ushort_t* __restrict__ Al_g,
    const ushort_t* __restrict__ Bh_g, const ushort_t* __restrict__ Bl_g,
    const float* __restrict__ R, float* __restrict__ C,
    ushort_t* __restrict__ Ch, ushort_t* __restrict__ Cl,
    float oscale, int M, int N, int K)
{
    extern __shared__ __align__(128) char sm[];
    const uint32_t sb = smem_u32(sm);
    const int tid = threadIdx.x;
    const int wid = tid >> 5, lane = tid & 31;
    const int m0 = blockIdx.y * 128, n0 = blockIdx.x * 128;
    const int wm = wid & 1, wn = wid >> 1;

    // stage-fill indices: 512 x 16B chunks per array, 2 per thread
    const int cid0 = tid * 2;

    float acc[4][4][4];
#pragma unroll
    for (int mi = 0; mi < 4; mi++)
#pragma unroll
        for (int nj = 0; nj < 4; nj++)
#pragma unroll
            for (int e = 0; e < 4; e++) acc[mi][nj][e] = 0.f;

    const int l8   = lane & 7;
    const int arow = ((lane >> 3) & 1) * 8 + l8;
    const int acol = ((lane >> 4) & 1) * 16;
    // x4 B addressing: groups 0-7/8-15 -> first n-tile (k0/k8), 16-23/24-31 -> second
    const int b4row = ((lane >> 4) & 1) * 8 + l8;
    const int b4col = ((lane >> 3) & 1) * 16;

    const int nchunks = K >> 5;

    // issue stage kc into buffer kc&1
    auto issue = [&](int kc) {
        const int kk = kc << 5;
        const uint32_t sbase = sb + (uint32_t)(kc & 1) * STAGE;
#pragma unroll
        for (int u = 0; u < 2; u++) {
            int cid = cid0 + u;              // 0..511
            int row = cid >> 2, c16 = cid & 3;
            uint32_t so = sbase + (uint32_t)row * ROWB + c16 * 16;
            size_t ao = (size_t)(m0 + row) * K + kk + c16 * 8;
            size_t bo = (size_t)(n0 + row) * K + kk + c16 * 8;
            cp16(so,          Ah_g + ao);
            cp16(so +   AREG, Al_g + ao);
            cp16(so + 2*AREG, Bh_g + bo);
            cp16(so + 3*AREG, Bl_g + bo);
        }
        CP_COMMIT();
    };

    issue(0);

    for (int kc = 0; kc < nchunks; kc++) {
        if (kc + 1 < nchunks) { issue(kc + 1); CP_WAIT1(); }
        else                  { CP_WAIT0(); }
        __syncthreads();

        const uint32_t abase = sb + (uint32_t)(kc & 1) * STAGE;
        const uint32_t bbase = abase + 2 * AREG;
#pragma unroll
        for (int s = 0; s < 2; s++) {
            uint32_t bhf[4][2], blf[4][2];
#pragma unroll
            for (int njp = 0; njp < 2; njp++) {
                uint32_t baddr = bbase + (uint32_t)(wn*32 + njp*16 + b4row) * ROWB
                               + s*32 + b4col;
                ldsm_x4(bhf[2*njp][0], bhf[2*njp][1],
                        bhf[2*njp+1][0], bhf[2*njp+1][1], baddr);
                ldsm_x4(blf[2*njp][0], blf[2*njp][1],
                        blf[2*njp+1][0], blf[2*njp+1][1], baddr + AREG);
            }
            uint32_t af[4][4], afl[4][4];
#pragma unroll
            for (int mi = 0; mi < 4; mi++) {
                uint32_t aaddr = abase + (uint32_t)(wm*64 + mi*16 + arow) * ROWB
                               + s*32 + acol;
                ldsm_x4(af[mi][0], af[mi][1], af[mi][2], af[mi][3], aaddr);
                ldsm_x4(afl[mi][0], afl[mi][1], afl[mi][2], afl[mi][3], aaddr + AREG);
            }
#pragma unroll
            for (int mi = 0; mi < 4; mi++)
#pragma unroll
                for (int nj = 0; nj < 4; nj++)
                    mma16816(acc[mi][nj], af[mi], bhf[nj]);   // hi*hi
#pragma unroll
            for (int mi = 0; mi < 4; mi++)
#pragma unroll
                for (int nj = 0; nj < 4; nj++)
                    mma16816(acc[mi][nj], af[mi], blf[nj]);   // hi*lo
#pragma unroll
            for (int mi = 0; mi < 4; mi++)
#pragma unroll
                for (int nj = 0; nj < 4; nj++)
                    mma16816(acc[mi][nj], afl[mi], bhf[nj]);  // lo*hi
        }
        __syncthreads();
    }

#pragma unroll
    for (int mi = 0; mi < 4; mi++) {
#pragma unroll
        for (int nj = 0; nj < 4; nj++) {
            int r0  = m0 + wm*64 + mi*16 + (lane >> 2);
            int col = n0 + wn*32 + nj*8 + (lane & 3) * 2;
            size_t o0 = (size_t)r0 * N + col;
            size_t o1 = (size_t)(r0 + 8) * N + col;
            if (SPLIT) {
                uint32_t h0, l0, h1, l1;
                split2(acc[mi][nj][0]*oscale, acc[mi][nj][1]*oscale, h0, l0);
                split2(acc[mi][nj][2]*oscale, acc[mi][nj][3]*oscale, h1, l1);
                *(uint32_t*)(Ch + o0) = h0;
                *(uint32_t*)(Cl + o0) = l0;
                *(uint32_t*)(Ch + o1) = h1;
                *(uint32_t*)(Cl + o1) = l1;
            } else {
                float2 v01, v23;
                v01.x = acc[mi][nj][0]; v01.y = acc[mi][nj][1];
                v23.x = acc[mi][nj][2]; v23.y = acc[mi][nj][3];
                float2 q0 = *(const float2*)(R + o0);
                float2 q1 = *(const float2*)(R + o1);
                v01.x += q0.x; v01.y += q0.y;
                v23.x += q1.x; v23.y += q1.y;
                *(float2*)(C + o0) = v01;
                *(float2*)(C + o1) = v23;
            }
        }
    }
}

// ---------------------------------------------------------------------------
// mma flash attention. Block: 128 queries x head x batch, 256 threads (8 warps,
// 16 q-rows each), 2 CTA/SM. 32 kv tiles of 64 keys, cp.async double-buffered.
// S = Qh.Kh + Qh.Kl + Ql.Kh ; PV = Ph.Vh + Ph.Vl + Pl.Vh.
// K fragments loaded as x4 (two n-tiles per LDSM). Epilogue writes split AV.
// ---------------------------------------------------------------------------
#define AROW 144
#define QH_OFF 0
#define QL_OFF 18432
#define KVBUF_OFF 36864
#define KVBUF_SZ  36864
#define ATTN_SMEM (KVBUF_OFF + 2*KVBUF_SZ)   // 110592

__global__ __launch_bounds__(256, 2) void attn_mma(
    const ushort_t* __restrict__ Qh, const ushort_t* __restrict__ Ql,
    const ushort_t* __restrict__ KVh, const ushort_t* __restrict__ KVl,
    ushort_t* __restrict__ AVh, ushort_t* __restrict__ AVl)
{
    extern __shared__ __align__(128) char sm[];
    const uint32_t sb = smem_u32(sm);
    const int qt = blockIdx.x, n = blockIdx.y, b = blockIdx.z;
    const int tid = threadIdx.x;
    const int wid = tid >> 5, lane = tid & 31;

    const int l8   = lane & 7;
    const int arow = ((lane >> 3) & 1) * 8 + l8;
    const int acol = ((lane >> 4) & 1) * 16;
    const int b4row = ((lane >> 4) & 1) * 8 + l8;
    const int b4col = ((lane >> 3) & 1) * 16;

    {
        int c0 = tid * 4;
#pragma unroll
        for (int u = 0; u < 4; u++) {
            int cid = c0 + u;
            int row = cid >> 3, c16 = cid & 7;
            size_t grow = (size_t)(qt*128 + row) * BB + b;
            size_t goff = grow * DM + n * DH + c16 * 8;
            cp16(sb + QH_OFF + row*AROW + c16*16, Qh + goff);
            cp16(sb + QL_OFF + row*AROW + c16*16, Ql + goff);
        }
    }
    {
        int c0 = tid * 2;
#pragma unroll
        for (int u = 0; u < 2; u++) {
            int cid = c0 + u;
            int row = cid >> 3, c16 = cid & 7;
            size_t gr = (size_t)(row) * BB + b;
            size_t ko = gr * (2*DM) + n * DH + c16 * 8;
            size_t vo = ko + DM;
            uint32_t so = sb + KVBUF_OFF + row*AROW + c16*16;
            cp16(so,         KVh + ko);
            cp16(so +  9216, KVl + ko);
            cp16(so + 18432, KVh + vo);
            cp16(so + 27648, KVl + vo);
        }
    }
    CP_COMMIT();

    float o[8][4];
#pragma unroll
    for (int dj = 0; dj < 8; dj++)
#pragma unroll
        for (int e = 0; e < 4; e++) o[dj][e] = 0.f;
    float m0 = -1e30f, m1 = -1e30f, lac0 = 0.f, lac1 = 0.f;

    for (int jt = 0; jt < KVL/64; jt++) {
        if (jt + 1 < KVL/64) {
            uint32_t bufn = sb + KVBUF_OFF + (uint32_t)((jt+1) & 1) * KVBUF_SZ;
            int c0 = tid * 2;
#pragma unroll
            for (int u = 0; u < 2; u++) {
                int cid = c0 + u;
                int row = cid >> 3, c16 = cid & 7;
                size_t gr = (size_t)((jt+1)*64 + row) * BB + b;
                size_t ko = gr * (2*DM) + n * DH + c16 * 8;
                size_t vo = ko + DM;
                uint32_t so = bufn + row*AROW + c16*16;
                cp16(so,         KVh + ko);
                cp16(so +  9216, KVl + ko);
                cp16(so + 18432, KVh + vo);
                cp16(so + 27648, KVl + vo);
            }
            CP_COMMIT();
            CP_WAIT1();
        } else {
            CP_WAIT0();
        }
        __syncthreads();

        const uint32_t kb = sb + KVBUF_OFF + (uint32_t)(jt & 1) * KVBUF_SZ;
        const uint32_t vb = kb + 18432;

        float s[8][4];
#pragma unroll
        for (int nj = 0; nj < 8; nj++)
#pragma unroll
            for (int e = 0; e < 4; e++) s[nj][e] = 0.f;

#pragma unroll
        for (int ks = 0; ks < 4; ks++) {
            uint32_t qf[4], qfl[4];
            uint32_t qaddr = sb + QH_OFF + (uint32_t)(wid*16 + arow)*AROW + ks*32 + acol;
            ldsm_x4(qf[0], qf[1], qf[2], qf[3], qaddr);
            ldsm_x4(qfl[0], qfl[1], qfl[2], qfl[3], qaddr + (QL_OFF - QH_OFF));
#pragma unroll
            for (int njp = 0; njp < 4; njp++) {
                uint32_t kh[4], kl[4];
                uint32_t kaddr = kb + (uint32_t)(njp*16 + b4row)*AROW + ks*32 + b4col;
                ldsm_x4(kh[0], kh[1], kh[2], kh[3], kaddr);
                ldsm_x4(kl[0], kl[1], kl[2], kl[3], kaddr + 9216);
                mma16816(s[2*njp],   qf,  kh);
                mma16816(s[2*njp+1], qf,  kh + 2);
                mma16816(s[2*njp],   qf,  kl);
                mma16816(s[2*njp+1], qf,  kl + 2);
                mma16816(s[2*njp],   qfl, kh);
                mma16816(s[2*njp+1], qfl, kh + 2);
            }
        }

        float rmax0 = -1e30f, rmax1 = -1e30f;
#pragma unroll
        for (int nj = 0; nj < 8; nj++) {
            rmax0 = fmaxf(rmax0, fmaxf(s[nj][0], s[nj][1]));
            rmax1 = fmaxf(rmax1, fmaxf(s[nj][2], s[nj][3]));
        }
        rmax0 = fmaxf(rmax0, __shfl_xor_sync(0xffffffffu, rmax0, 1));
        rmax0 = fmaxf(rmax0, __shfl_xor_sync(0xffffffffu, rmax0, 2));
        rmax1 = fmaxf(rmax1, __shfl_xor_sync(0xffffffffu, rmax1, 1));
        rmax1 = fmaxf(rmax1, __shfl_xor_sync(0xffffffffu, rmax1, 2));
        float mn0 = fmaxf(m0, rmax0), mn1 = fmaxf(m1, rmax1);
        float fc0 = __expf(m0 - mn0), fc1 = __expf(m1 - mn1);
        m0 = mn0; m1 = mn1;
        float sum0 = 0.f, sum1 = 0.f;
#pragma unroll
        for (int nj = 0; nj < 8; nj++) {
            float p0 = __expf(s[nj][0] - mn0);
            float p1 = __expf(s[nj][1] - mn0);
            float p2 = __expf(s[nj][2] - mn1);
            float p3 = __expf(s[nj][3] - mn1);
            s[nj][0] = p0; s[nj][1] = p1; s[nj][2] = p2; s[nj][3] = p3;
            sum0 += p0 + p1; sum1 += p2 + p3;
        }
        sum0 += __shfl_xor_sync(0xffffffffu, sum0, 1);
        sum0 += __shfl_xor_sync(0xffffffffu, sum0, 2);
        sum1 += __shfl_xor_sync(0xffffffffu, sum1, 1);
        sum1 += __shfl_xor_sync(0xffffffffu, sum1, 2);
        lac0 = lac0 * fc0 + sum0;
        lac1 = lac1 * fc1 + sum1;
#pragma unroll
        for (int dj = 0; dj < 8; dj++) {
            o[dj][0] *= fc0; o[dj][1] *= fc0;
            o[dj][2] *= fc1; o[dj][3] *= fc1;
        }

#pragma unroll
        for (int ks = 0; ks < 4; ks++) {
            uint32_t ah[4], al[4];
            split2(s[2*ks][0],   s[2*ks][1],   ah[0], al[0]);
            split2(s[2*ks][2],   s[2*ks][3],   ah[1], al[1]);
            split2(s[2*ks+1][0], s[2*ks+1][1], ah[2], al[2]);
            split2(s[2*ks+1][2], s[2*ks+1][3], ah[3], al[3]);
#pragma unroll
            for (int djp = 0; djp < 4; djp++) {
                int dj = djp * 2;
                int mm = lane >> 3;
                uint32_t vaddr = vb
                    + (uint32_t)(ks*16 + (mm & 1)*8 + l8) * AROW
                    + (uint32_t)(dj + (mm >> 1)) * 16;
                uint32_t vh[4], vl[4];
                ldsm_x4t(vh[0], vh[1], vh[2], vh[3], vaddr);
                ldsm_x4t(vl[0], vl[1], vl[2], vl[3], vaddr + 9216);
                mma16816(o[dj],   ah, vh);
                mma16816(o[dj+1], ah, vh + 2);
                mma16816(o[dj],   ah, vl);
                mma16816(o[dj+1], ah, vl + 2);
                mma16816(o[dj],   al, vh);
                mma16816(o[dj+1], al, vh + 2);
            }
        }
        __syncthreads();
    }

    // ---- epilogue: divide by l, split to bf16 hi/lo ----
    float inv0 = 1.f / lac0, inv1 = 1.f / lac1;
    int g = lane >> 2;
    size_t gr0 = ((size_t)(qt*128 + wid*16 + g)) * BB + b;
    size_t gr1 = gr0 + (size_t)8 * BB;
    int colb = n * DH + (lane & 3) * 2;
#pragma unroll
    for (int dj = 0; dj < 8; dj++) {
        uint32_t h0, l0, h1, l1;
        split2(o[dj][0] * inv0, o[dj][1] * inv0, h0, l0);
        split2(o[dj][2] * inv1, o[dj][3] * inv1, h1, l1);
        *(uint32_t*)(AVh + gr0 * DM + colb + dj*8) = h0;
        *(uint32_t*)(AVl + gr0 * DM + colb + dj*8) = l0;
        *(uint32_t*)(AVh + gr1 * DM + colb + dj*8) = h1;
        *(uint32_t*)(AVl + gr1 * DM + colb + dj*8) = l1;
    }
}

// ---------------------------------------------------------------------------
// LayerNorm over rows of 1024.
// ---------------------------------------------------------------------------
__global__ __launch_bounds__(256) void ln_kernel(
    const float* __restrict__ Y, const float* __restrict__ gamma,
    const float* __restrict__ beta, float* __restrict__ out)
{
    __shared__ float red1[8];
    __shared__ float red2[8];
    const int row = blockIdx.x, tid = threadIdx.x;
    const float* y = Y + (size_t)row * DM;
    float v[4];
#pragma unroll
    for (int u = 0; u < 4; u++) v[u] = y[tid + u*256];

    float s = v[0] + v[1] + v[2] + v[3];
#pragma unroll
    for (int m = 16; m; m >>= 1) s += __shfl_xor_sync(0xffffffffu, s, m);
    if ((tid & 31) == 0) red1[tid >> 5] = s;
    __syncthreads();
    float tot = 0.f;
#pragma unroll
    for (int w = 0; w < 8; w++) tot += red1[w];
    float mu = tot * (1.f / DM);

    float q = 0.f;
#pragma unroll
    for (int u = 0; u < 4; u++) { float d = v[u] - mu; q += d * d; }
#pragma unroll
    for (int m = 16; m; m >>= 1) q += __shfl_xor_sync(0xffffffffu, q, m);
    if ((tid & 31) == 0) red2[tid >> 5] = q;
    __syncthreads();
    float qtot = 0.f;
#pragma unroll
    for (int w = 0; w < 8; w++) qtot += red2[w];
    float inv = rsqrtf(qtot * (1.f / DM) + 1e-5f);

#pragma unroll
    for (int u = 0; u < 4; u++) {
        int cix = tid + u*256;
        out[(size_t)row * DM + cix] = (v[u] - mu) * inv * gamma[cix] + beta[cix];
    }
}

// ---------------------------------------------------------------------------
extern "C" void kernel_launch(void* const* d_in, const int* in_sizes, int n_in,
                              void* d_out, int out_size)
{
    const float* h     = (const float*)d_in[0];
    const float* c     = (const float*)d_in[1];
    const float* Wq    = (const float*)d_in[2];
    const float* Wkv   = (const float*)d_in[3];
    const float* Wo    = (const float*)d_in[4];
    const float* gamma = (const float*)d_in[5];
    const float* beta  = (const float*)d_in[6];
    float* out = (float*)d_out;

    ushort_t *hh, *hl, *ch, *cl, *Wqh, *Wql, *Wkvh, *Wkvl, *Woh, *Wol;
    ushort_t *Qh, *Ql, *KVh, *KVl, *AVh, *AVl;
    float *Yb;
    cudaGetSymbolAddress((void**)&hh,   g_hh);
    cudaGetSymbolAddress((void**)&hl,   g_hl);
    cudaGetSymbolAddress((void**)&ch,   g_ch);
    cudaGetSymbolAddress((void**)&cl,   g_cl);
    cudaGetSymbolAddress((void**)&Wqh,  g_Wqh);
    cudaGetSymbolAddress((void**)&Wql,  g_Wql);
    cudaGetSymbolAddress((void**)&Wkvh, g_Wkvh);
    cudaGetSymbolAddress((void**)&Wkvl, g_Wkvl);
    cudaGetSymbolAddress((void**)&Woh,  g_Woh);
    cudaGetSymbolAddress((void**)&Wol,  g_Wol);
    cudaGetSymbolAddress((void**)&Qh,   g_Qh);
    cudaGetSymbolAddress((void**)&Ql,   g_Ql);
    cudaGetSymbolAddress((void**)&KVh,  g_KVh);
    cudaGetSymbolAddress((void**)&KVl,  g_KVl);
    cudaGetSymbolAddress((void**)&AVh,  g_AVh);
    cudaGetSymbolAddress((void**)&AVl,  g_AVl);
    cudaGetSymbolAddress((void**)&Yb,   g_Y);

    cudaFuncSetAttribute(mma_gemm<0>,
                         cudaFuncAttributeMaxDynamicSharedMemorySize, GEMM_SMEM);
    cudaFuncSetAttribute(mma_gemm<1>,
                         cudaFuncAttributeMaxDynamicSharedMemorySize, GEMM_SMEM);
    cudaFuncSetAttribute(attn_mma,
                         cudaFuncAttributeMaxDynamicSharedMemorySize, ATTN_SMEM);

    // ---- pre-split all fp32 inputs into bf16 hi/lo ----
    split_kernel<<<QROWS*DM/1024, 256>>>(h,   hh,   hl,   QROWS*DM);
    split_kernel<<<KVROWS*DM/1024, 256>>>(c,  ch,   cl,   KVROWS*DM);
    split_kernel<<<DM*DM/1024, 256>>>(Wq,     Wqh,  Wql,  DM*DM);
    split_kernel<<<2*DM*DM/1024, 256>>>(Wkv,  Wkvh, Wkvl, 2*DM*DM);
    split_kernel<<<DM*DM/1024, 256>>>(Wo,     Woh,  Wol,  DM*DM);

    // Q = (h @ Wq^T) * ATTN_SCALE -> bf16 hi/lo   [4096 x 1024]
    mma_gemm<1><<<dim3(DM/128, QROWS/128), 256, GEMM_SMEM>>>(
        hh, hl, Wqh, Wql, nullptr, nullptr, Qh, Ql, ATTN_SCALE, QROWS, DM, DM);
    // KV = c @ Wkv^T -> bf16 hi/lo                [8192 x 2048]
    mma_gemm<1><<<dim3(2*DM/128, KVROWS/128), 256, GEMM_SMEM>>>(
        ch, cl, Wkvh, Wkvl, nullptr, nullptr, KVh, KVl, 1.0f, KVROWS, 2*DM, DM);
    // attention -> AV split                       [4096 x 1024]
    attn_mma<<<dim3(QL/128, NH, BB), 256, ATTN_SMEM>>>(Qh, Ql, KVh, KVl, AVh, AVl);
    // Y = AV @ Wo^T + h                           [4096 x 1024]
    mma_gemm<0><<<dim3(DM/128, QROWS/128), 256, GEMM_SMEM>>>(
        AVh, AVl, Woh, Wol, h, Yb, nullptr, nullptr, 1.0f, QROWS, DM, DM);
    // out = LN(Y)
    ln_kernel<<<QROWS, 256>>>(Yb, gamma, beta, out);
}